// round 5
// baseline (speedup 1.0000x reference)
#include <cuda_runtime.h>
#include <cuda_bf16.h>
#include <math.h>
#include <stdint.h>

// ---------------- problem constants ----------------
#define BB 8
#define NN 5000
#define EE 80000
#define IND 30
#define HH 4
#define DD 64
#define HD 256
#define OUTD 3
#define TSTEPS 5
#define EPSBN 1e-5f
#define MROWS (BB*NN)   // 40000

// GEMM tiling
#define TM 128
#define TN 128
#define KC 64           // k chunk
#define ASTR 72         // padded A smem stride (bf16) -> conflict-free ldmatrix
#define BSTR 264        // padded B smem stride (bf16), full K=256 resident
#define NPART 64        // BN partial slots
#define FC_ROWS 16

// dynamic smem: Bhi + Blo (full K) + 2 double-buffered A (hi+lo)
#define B_BYTES (128 * BSTR * 2)
#define A_BYTES (128 * ASTR * 2)
#define GSM_BYTES (2 * B_BYTES + 4 * A_BYTES)   // 135168 + 73728 = 208896

// ---------------- device scratch ----------------
__device__ float g_x[MROWS * IND];
__device__ float g_h[MROWS * HD];
__device__ float g_hout[MROWS * HD];
__device__ float g_el[MROWS * HH];
__device__ float g_er[MROWS * HH];
__device__ int   g_rowstart[NN + 1];
__device__ int   g_csr_src[EE];
__device__ float g_part[NPART * HD];
__device__ float g_partsq[NPART * HD];
__device__ float g_scale[HD];
__device__ float g_shift[HD];
__device__ __nv_bfloat16 g_wthi[3 * HD * HD];   // [l][n][k]
__device__ __nv_bfloat16 g_wtlo[3 * HD * HD];

__device__ __forceinline__ float lk(float x, float s) { return x > 0.f ? x : s * x; }

__device__ __forceinline__ uint32_t s2u(const void* p) {
    uint32_t a;
    asm("{ .reg .u64 t; cvta.to.shared.u64 t, %1; cvt.u32.u64 %0, t; }" : "=r"(a) : "l"(p));
    return a;
}
__device__ __forceinline__ void ldsm4(uint32_t* r, uint32_t a) {
    asm volatile("ldmatrix.sync.aligned.m8n8.x4.shared.b16 {%0,%1,%2,%3}, [%4];"
                 : "=r"(r[0]), "=r"(r[1]), "=r"(r[2]), "=r"(r[3]) : "r"(a));
}
__device__ __forceinline__ void mma16816(float* c, const uint32_t* a, const uint32_t* b) {
    asm volatile(
        "mma.sync.aligned.m16n8k16.row.col.f32.bf16.bf16.f32 "
        "{%0,%1,%2,%3}, {%4,%5,%6,%7}, {%8,%9}, {%0,%1,%2,%3};"
        : "+f"(c[0]), "+f"(c[1]), "+f"(c[2]), "+f"(c[3])
        : "r"(a[0]), "r"(a[1]), "r"(a[2]), "r"(a[3]), "r"(b[0]), "r"(b[1]));
}

// ---------------- CSR build: one block does count + scan + fill ----------------
__global__ __launch_bounds__(1024) void k_csr(const int* __restrict__ src,
                                              const int* __restrict__ dst) {
    __shared__ int s_start[NN];
    __shared__ int s_tmp[1024];
    const int t = threadIdx.x;

    for (int i = t; i < NN; i += 1024) s_start[i] = 0;
    __syncthreads();
    for (int e = t; e < EE; e += 1024) atomicAdd(&s_start[dst[e]], 1);
    __syncthreads();

    int carry = 0;
    for (int base = 0; base < NN; base += 1024) {
        int v = (base + t < NN) ? s_start[base + t] : 0;
        s_tmp[t] = v;
        __syncthreads();
        for (int off = 1; off < 1024; off <<= 1) {
            int x = (t >= off) ? s_tmp[t - off] : 0;
            __syncthreads();
            s_tmp[t] += x;
            __syncthreads();
        }
        int incl = s_tmp[t];
        int tot = s_tmp[1023];
        __syncthreads();
        if (base + t < NN) {
            int ex = carry + incl - v;
            s_start[base + t] = ex;
            g_rowstart[base + t] = ex;
        }
        carry += tot;
    }
    if (t == 0) g_rowstart[NN] = carry;
    __syncthreads();

    // fill: s_start doubles as running cursor
    for (int e = t; e < EE; e += 1024) {
        int v = dst[e];
        int p = atomicAdd(&s_start[v], 1);
        g_csr_src[p] = src[e];
    }
}

__global__ void k_copyx(const float* __restrict__ xx) {
    int i = blockIdx.x * blockDim.x + threadIdx.x;
    if (i < MROWS * IND) g_x[i] = xx[i];
}

// ---------------- W transpose + bf16 split  (W[k][n] -> wt[n][k]) ----------------
__global__ void k_wprep(const float* __restrict__ W1, const float* __restrict__ W2,
                        const float* __restrict__ W3) {
    int k = blockIdx.x;
    int l = blockIdx.y;
    int n = threadIdx.x;
    const float* W = (l == 0) ? W1 : (l == 1) ? W2 : W3;
    float v = W[k * HD + n];
    __nv_bfloat16 h = __float2bfloat16(v);
    float lo = v - __bfloat162float(h);
    int o = l * HD * HD + n * HD + k;
    g_wthi[o] = h;
    g_wtlo[o] = __float2bfloat16(lo);
}

// ---------------- layer-0 FC (K=30), 16 rows/block, fused el/er ----------------
__global__ __launch_bounds__(256) void k_fc0(const float* __restrict__ W,
                                             const float* __restrict__ al,
                                             const float* __restrict__ ar) {
    __shared__ float sW[IND * HD];
    __shared__ float sx[FC_ROWS * IND];
    __shared__ float pel[FC_ROWS][8], per_[FC_ROWS][8];
    const int t = threadIdx.x;
    const int m0 = blockIdx.x * FC_ROWS;
    const int w = t >> 5, lane = t & 31;

    for (int i = t; i < IND * HD; i += 256) sW[i] = W[i];
    for (int i = t; i < FC_ROWS * IND; i += 256) sx[i] = g_x[m0 * IND + i];
    __syncthreads();

    const float alv = __ldg(&al[t]);
    const float arv = __ldg(&ar[t]);

#pragma unroll
    for (int r = 0; r < FC_ROWS; r++) {
        float acc = 0.f;
#pragma unroll
        for (int k = 0; k < IND; k++) acc = fmaf(sx[r * IND + k], sW[k * HD + t], acc);
        g_h[(size_t)(m0 + r) * HD + t] = acc;
        float ve = acc * alv, vr = acc * arv;
#pragma unroll
        for (int off = 16; off; off >>= 1) {
            ve += __shfl_xor_sync(0xffffffffu, ve, off);
            vr += __shfl_xor_sync(0xffffffffu, vr, off);
        }
        if (lane == 0) { pel[r][w] = ve; per_[r][w] = vr; }
    }
    __syncthreads();
    if (t < FC_ROWS * HH) {
        int r = t >> 2, h = t & 3;
        g_el[(m0 + r) * HH + h] = pel[r][2 * h] + pel[r][2 * h + 1];
        g_er[(m0 + r) * HH + h] = per_[r][2 * h] + per_[r][2 * h + 1];
    }
}

// ---------------- HMMA GEMM: g_h = lrelu(BN(g_hout)) @ W, fused el/er ----------------
// B (hi+lo, full K) resident in smem; A double-buffered; 1 sync per chunk.
__global__ __launch_bounds__(256) void k_gemm(int wsel, const float* __restrict__ al,
                                              const float* __restrict__ ar) {
    extern __shared__ char sm[];
    __shared__ float s_sc[HD], s_sh[HD];
    __nv_bfloat16* Bhi = (__nv_bfloat16*)sm;
    __nv_bfloat16* Blo = Bhi + 128 * BSTR;
    __nv_bfloat16* Abase = Blo + 128 * BSTR;
    // buffers: [buf][hi/lo][128*ASTR]
    const uint32_t uBhi = s2u(Bhi), uBlo = s2u(Blo);
    const uint32_t uA = s2u(Abase);

    const int t = threadIdx.x;
    const int lane = t & 31, warp = t >> 5;
    const int bx = blockIdx.x, by = blockIdx.y;
    const int row0 = by * TM, col0 = bx * TN;
    const int warp_m = (warp >> 1) * 32;
    const int warp_n = (warp & 1) * 64;
    const int head = bx * 2 + (warp & 1);

    s_sc[t] = g_scale[t];             s_sh[t] = g_shift[t];
    if (t < HD - 256 + 256) {}        // no-op
    s_sc[(t + 128) & 255] = g_scale[(t + 128) & 255];
    s_sh[(t + 128) & 255] = g_shift[(t + 128) & 255];

    const __nv_bfloat16* wh = g_wthi + wsel * HD * HD;
    const __nv_bfloat16* wl = g_wtlo + wsel * HD * HD;

    // ---- load full B (128 n-rows x 256 k) hi+lo ----
    {
        int n = t >> 1, kh = (t & 1) * 128;
        int gn = col0 + n;
        const uint4* ph = (const uint4*)&wh[gn * HD + kh];
        const uint4* pl = (const uint4*)&wl[gn * HD + kh];
#pragma unroll
        for (int q = 0; q < 16; q++) {
            *(uint4*)&Bhi[n * BSTR + kh + 8 * q] = __ldg(&ph[q]);
            *(uint4*)&Blo[n * BSTR + kh + 8 * q] = __ldg(&pl[q]);
        }
    }

    float c[2][8][4];
#pragma unroll
    for (int i = 0; i < 2; i++)
#pragma unroll
        for (int j = 0; j < 8; j++)
#pragma unroll
            for (int q = 0; q < 4; q++) c[i][j][q] = 0.f;

    // ldmatrix address components
    const int a_row = ((lane >> 3) & 1) * 8 + (lane & 7);
    const int a_kof = (lane >> 4) * 8;
    const int b_nsel = (lane >> 4) & 1;
    const int b_ksel = (lane >> 3) & 1;
    const int b_row = (lane & 7);

    // A conversion lambda: chunk ch -> buffer bf
    auto convA = [&](int ch, int bf) {
        __nv_bfloat16* Ahi = Abase + bf * 2 * 128 * ASTR;
        __nv_bfloat16* Alo = Ahi + 128 * ASTR;
        const int k0 = ch * KC;
        int r = t >> 1, c0i = (t & 1) * 32;
        int grow = row0 + r;
        float x[32];
        if (grow < MROWS) {
            const float4* p = (const float4*)&g_hout[(size_t)grow * HD + k0 + c0i];
#pragma unroll
            for (int q = 0; q < 8; q++) {
                float4 v = p[q];
                x[4 * q + 0] = v.x; x[4 * q + 1] = v.y; x[4 * q + 2] = v.z; x[4 * q + 3] = v.w;
            }
        } else {
#pragma unroll
            for (int j = 0; j < 32; j++) x[j] = 0.f;
        }
#pragma unroll
        for (int j = 0; j < 32; j++) {
            float v = fmaf(x[j], s_sc[k0 + c0i + j], s_sh[k0 + c0i + j]);
            x[j] = v > 0.f ? v : 0.01f * v;
        }
#pragma unroll
        for (int q = 0; q < 4; q++) {
            union { __nv_bfloat16 b[8]; uint4 u; } uh, ul;
#pragma unroll
            for (int j = 0; j < 8; j++) {
                float xv = x[8 * q + j];
                __nv_bfloat16 h = __float2bfloat16(xv);
                uh.b[j] = h;
                ul.b[j] = __float2bfloat16(xv - __bfloat162float(h));
            }
            *(uint4*)&Ahi[r * ASTR + c0i + 8 * q] = uh.u;
            *(uint4*)&Alo[r * ASTR + c0i + 8 * q] = ul.u;
        }
    };

    convA(0, 0);
    __syncthreads();

    for (int ch = 0; ch < 4; ch++) {
        const int bf = ch & 1;
        const uint32_t uAhi = uA + (uint32_t)(bf * 2 * 128 * ASTR * 2);
        const uint32_t uAlo = uAhi + 128 * ASTR * 2;
#pragma unroll
        for (int ks = 0; ks < 4; ks++) {
            const int kg = ch * 4 + ks;
            uint32_t afh[2][4], afl[2][4];
            uint32_t bfh[8][2], bfl[8][2];
#pragma unroll
            for (int mt = 0; mt < 2; mt++) {
                uint32_t off = (uint32_t)(((warp_m + mt * 16 + a_row) * ASTR + 16 * ks + a_kof) * 2);
                ldsm4(afh[mt], uAhi + off);
                ldsm4(afl[mt], uAlo + off);
            }
#pragma unroll
            for (int p = 0; p < 4; p++) {
                uint32_t off = (uint32_t)(((warp_n + (2 * p + b_nsel) * 8 + b_row) * BSTR + 16 * kg + 8 * b_ksel) * 2);
                uint32_t r4[4];
                ldsm4(r4, uBhi + off);
                bfh[2 * p][0] = r4[0]; bfh[2 * p][1] = r4[1];
                bfh[2 * p + 1][0] = r4[2]; bfh[2 * p + 1][1] = r4[3];
                ldsm4(r4, uBlo + off);
                bfl[2 * p][0] = r4[0]; bfl[2 * p][1] = r4[1];
                bfl[2 * p + 1][0] = r4[2]; bfl[2 * p + 1][1] = r4[3];
            }
#pragma unroll
            for (int mt = 0; mt < 2; mt++)
#pragma unroll
                for (int nt = 0; nt < 8; nt++) {
                    mma16816(c[mt][nt], afh[mt], bfh[nt]);   // hi*hi
                    mma16816(c[mt][nt], afh[mt], bfl[nt]);   // hi*lo
                    mma16816(c[mt][nt], afl[mt], bfh[nt]);   // lo*hi
                }
        }
        if (ch < 3) {
            convA(ch + 1, (ch + 1) & 1);   // overlaps tensor-pipe drain
            __syncthreads();
        }
    }

    // ---- epilogue: store D + fused el/er (warp covers exactly one head) ----
    float elacc[2][2] = {{0.f, 0.f}, {0.f, 0.f}};
    float eracc[2][2] = {{0.f, 0.f}, {0.f, 0.f}};
    const int qn = 2 * (lane & 3);
    const int g = lane >> 2;
#pragma unroll
    for (int mt = 0; mt < 2; mt++) {
#pragma unroll
        for (int nt = 0; nt < 8; nt++) {
            float v0 = c[mt][nt][0], v1 = c[mt][nt][1];
            float v2 = c[mt][nt][2], v3 = c[mt][nt][3];
            int cih = nt * 8 + qn;
            float a0 = __ldg(&al[head * DD + cih]), a1 = __ldg(&al[head * DD + cih + 1]);
            float r0 = __ldg(&ar[head * DD + cih]), r1 = __ldg(&ar[head * DD + cih + 1]);
            elacc[mt][0] = fmaf(v0, a0, fmaf(v1, a1, elacc[mt][0]));
            elacc[mt][1] = fmaf(v2, a0, fmaf(v3, a1, elacc[mt][1]));
            eracc[mt][0] = fmaf(v0, r0, fmaf(v1, r1, eracc[mt][0]));
            eracc[mt][1] = fmaf(v2, r0, fmaf(v3, r1, eracc[mt][1]));
            int gcol = col0 + warp_n + cih;
            int grow0 = row0 + warp_m + mt * 16 + g;
            int grow1 = grow0 + 8;
            if (grow0 < MROWS) *(float2*)&g_h[(size_t)grow0 * HD + gcol] = make_float2(v0, v1);
            if (grow1 < MROWS) *(float2*)&g_h[(size_t)grow1 * HD + gcol] = make_float2(v2, v3);
        }
    }
#pragma unroll
    for (int mt = 0; mt < 2; mt++)
#pragma unroll
        for (int half = 0; half < 2; half++) {
            float e = elacc[mt][half], r = eracc[mt][half];
            e += __shfl_xor_sync(0xffffffffu, e, 1);
            e += __shfl_xor_sync(0xffffffffu, e, 2);
            r += __shfl_xor_sync(0xffffffffu, r, 1);
            r += __shfl_xor_sync(0xffffffffu, r, 2);
            int row = row0 + warp_m + mt * 16 + half * 8 + g;
            if ((lane & 3) == 0 && row < MROWS) {
                g_el[row * HH + head] = e;
                g_er[row * HH + head] = r;
            }
        }
}

// ---------------- edge softmax + aggregation + fused BN partial stats ----------------
__global__ __launch_bounds__(256) void k_agg() {
    const int bn = blockIdx.x;
    const int b  = bn / NN;
    const int v  = bn - b * NN;
    const int t  = threadIdx.x;
    const int hh = t >> 6;
    const int d  = t & 63;

    const int e0 = g_rowstart[v];
    const int deg = g_rowstart[v + 1] - e0;
    float* outp = g_hout + (size_t)bn * HD;
    if (deg == 0) { outp[t] = 0.f; return; }

    __shared__ float sh_er[HH];
    __shared__ float sh_m[HH];
    __shared__ float sh_is[HH];
    __shared__ float sh_w[HH][32];
    __shared__ int   sh_src[32];

    if (t < HH) sh_er[t] = g_er[bn * HH + t];
    __syncthreads();

    const int w = t >> 5, lane = t & 31;
    if (w < HH) {
        float mv = -INFINITY;
        for (int i = lane; i < deg; i += 32) {
            int s = g_csr_src[e0 + i];
            float e = lk(g_el[(b * NN + s) * HH + w] + sh_er[w], 0.2f);
            mv = fmaxf(mv, e);
        }
#pragma unroll
        for (int off = 16; off; off >>= 1) mv = fmaxf(mv, __shfl_xor_sync(0xffffffffu, mv, off));
        if (lane == 0) sh_m[w] = mv;
    }
    __syncthreads();
    if (w < HH) {
        float sum = 0.f;
        float m = sh_m[w];
        for (int i = lane; i < deg; i += 32) {
            int s = g_csr_src[e0 + i];
            float e = lk(g_el[(b * NN + s) * HH + w] + sh_er[w], 0.2f);
            sum += __expf(e - m);
        }
#pragma unroll
        for (int off = 16; off; off >>= 1) sum += __shfl_xor_sync(0xffffffffu, sum, off);
        if (lane == 0) sh_is[w] = 1.f / sum;
    }
    __syncthreads();

    float a0 = 0.f, a1 = 0.f, a2 = 0.f, a3 = 0.f;
    for (int base = 0; base < deg; base += 32) {
        int len = min(32, deg - base);
        if (t < 128) {
            int i = t & 31, h2 = t >> 5;
            if (i < len) {
                int s = g_csr_src[e0 + base + i];
                if (t < 32) sh_src[i] = s;
                float e = lk(g_el[(b * NN + s) * HH + h2] + sh_er[h2], 0.2f);
                sh_w[h2][i] = __expf(e - sh_m[h2]) * sh_is[h2];
            }
        }
        __syncthreads();
        int i = 0;
        for (; i + 4 <= len; i += 4) {
            int s0 = sh_src[i], s1 = sh_src[i + 1], s2 = sh_src[i + 2], s3 = sh_src[i + 3];
            float w0 = sh_w[hh][i], w1 = sh_w[hh][i + 1], w2 = sh_w[hh][i + 2], w3 = sh_w[hh][i + 3];
            float v0 = g_h[(((size_t)b * NN + s0) << 8) + (hh << 6) + d];
            float v1 = g_h[(((size_t)b * NN + s1) << 8) + (hh << 6) + d];
            float v2 = g_h[(((size_t)b * NN + s2) << 8) + (hh << 6) + d];
            float v3 = g_h[(((size_t)b * NN + s3) << 8) + (hh << 6) + d];
            a0 = fmaf(w0, v0, a0);
            a1 = fmaf(w1, v1, a1);
            a2 = fmaf(w2, v2, a2);
            a3 = fmaf(w3, v3, a3);
        }
        for (; i < len; i++) {
            int s0 = sh_src[i];
            a0 = fmaf(sh_w[hh][i], g_h[(((size_t)b * NN + s0) << 8) + (hh << 6) + d], a0);
        }
        __syncthreads();
    }
    float acc = (a0 + a1) + (a2 + a3);
    outp[t] = acc;
    int slot = (bn & (NPART - 1)) * HD + t;
    atomicAdd(&g_part[slot], acc);
    atomicAdd(&g_partsq[slot], acc * acc);
}

// ---------------- BatchNorm finalize (reads partials, zeroes them for next layer) ----------------
__global__ void k_bnfin(const float* __restrict__ gamma, const float* __restrict__ beta) {
    int c = threadIdx.x;
    float s = 0.f, sq = 0.f;
#pragma unroll
    for (int i = 0; i < NPART; i++) {
        s  += g_part[i * HD + c];
        sq += g_partsq[i * HD + c];
        g_part[i * HD + c] = 0.f;
        g_partsq[i * HD + c] = 0.f;
    }
    float inv = 1.f / (float)MROWS;
    float mu = s * inv;
    float var = sq * inv - mu * mu;
    float sc = gamma[c] * rsqrtf(var + EPSBN);
    g_scale[c] = sc;
    g_shift[c] = beta[c] - mu * sc;
}

// ---------------- output projection (applies last BN) + autoregressive shift ----------------
__global__ void k_proj(const float* __restrict__ Wo, const float* __restrict__ bo,
                       float* __restrict__ out, int step) {
    int bn = blockIdx.x;
    int w = threadIdx.x >> 5, lane = threadIdx.x & 31;
    __shared__ float sval[OUTD];
    const float* hp = g_hout + (size_t)bn * HD;
    float sum = 0.f;
#pragma unroll
    for (int k = lane; k < HD; k += 32) {
        float xv = fmaf(hp[k], g_scale[k], g_shift[k]);
        xv = xv > 0.f ? xv : 0.01f * xv;
        sum = fmaf(xv, Wo[k * OUTD + w], sum);
    }
#pragma unroll
    for (int off = 16; off; off >>= 1) sum += __shfl_xor_sync(0xffffffffu, sum, off);
    if (lane == 0) sval[w] = sum + bo[w];

    float keep = 0.f;
    if (threadIdx.x < IND - OUTD) keep = g_x[bn * IND + threadIdx.x + OUTD];
    __syncthreads();
    if (threadIdx.x < IND - OUTD) g_x[bn * IND + threadIdx.x] = keep;
    else if (threadIdx.x < IND) g_x[bn * IND + threadIdx.x] = sval[threadIdx.x - (IND - OUTD)];
    if (threadIdx.x < OUTD) out[(bn * TSTEPS + step) * OUTD + threadIdx.x] = sval[threadIdx.x];
}

// ---------------- launcher ----------------
extern "C" void kernel_launch(void* const* d_in, const int* in_sizes, int n_in,
                              void* d_out, int out_size) {
    const float* xx  = (const float*)d_in[0];
    const int*   src = (const int*)d_in[1];
    const int*   dst = (const int*)d_in[2];
    const float *W[4], *al[4], *ar[4], *gamma[4], *beta[4];
    for (int l = 0; l < 4; l++) {
        W[l]     = (const float*)d_in[3 + 5 * l];
        al[l]    = (const float*)d_in[4 + 5 * l];
        ar[l]    = (const float*)d_in[5 + 5 * l];
        gamma[l] = (const float*)d_in[6 + 5 * l];
        beta[l]  = (const float*)d_in[7 + 5 * l];
    }
    const float* W_out = (const float*)d_in[23];
    const float* b_out = (const float*)d_in[24];
    float* out = (float*)d_out;

    cudaFuncSetAttribute(k_gemm, cudaFuncAttributeMaxDynamicSharedMemorySize, GSM_BYTES);

    dim3 ggrid(HD / TN, (MROWS + TM - 1) / TM);

    // launch order chosen so the profiler's fixed capture slot (launch #4) = k_agg
    k_csr<<<1, 1024>>>(src, dst);                                // 1
    k_copyx<<<(MROWS * IND + 255) / 256, 256>>>(xx);             // 2
    k_fc0<<<MROWS / FC_ROWS, 256>>>(W[0], al[0], ar[0]);         // 3
    k_agg<<<MROWS, 256>>>();                                     // 4  <-- profiled
    k_wprep<<<dim3(HD, 3), HD>>>(W[1], W[2], W[3]);              // 5
    k_bnfin<<<1, HD>>>(gamma[0], beta[0]);                       // 6
    for (int l = 1; l < 4; l++) {
        k_gemm<<<ggrid, 256, GSM_BYTES>>>(l - 1, al[l], ar[l]);
        k_agg<<<MROWS, 256>>>();
        k_bnfin<<<1, HD>>>(gamma[l], beta[l]);
    }
    k_proj<<<MROWS, 96>>>(W_out, b_out, out, 0);

    for (int step = 1; step < TSTEPS; step++) {
        for (int l = 0; l < 4; l++) {
            if (l == 0)
                k_fc0<<<MROWS / FC_ROWS, 256>>>(W[0], al[0], ar[0]);
            else
                k_gemm<<<ggrid, 256, GSM_BYTES>>>(l - 1, al[l], ar[l]);
            k_agg<<<MROWS, 256>>>();
            k_bnfin<<<1, HD>>>(gamma[l], beta[l]);
        }
        k_proj<<<MROWS, 96>>>(W_out, b_out, out, step);
    }
}

// round 6
// speedup vs baseline: 1.0143x; 1.0143x over previous
#include <cuda_runtime.h>
#include <cuda_bf16.h>
#include <math.h>
#include <stdint.h>

// ---------------- problem constants ----------------
#define BB 8
#define NN 5000
#define EE 80000
#define IND 30
#define HH 4
#define DD 64
#define HD 256
#define OUTD 3
#define TSTEPS 5
#define EPSBN 1e-5f
#define MROWS (BB*NN)   // 40000

// GEMM tiling
#define TM 128
#define TN 128
#define KC 64
#define ASTR 72
#define BSTR 264
#define NPART 64
#define FC_ROWS 16

#define B_BYTES (128 * BSTR * 2)
#define A_BYTES (128 * ASTR * 2)
#define GSM_BYTES (2 * B_BYTES + 4 * A_BYTES)

// ---------------- device scratch ----------------
__device__ float g_x[MROWS * IND];
__device__ float g_h[MROWS * HD];
__device__ float g_hout[MROWS * HD];
__device__ float g_el[MROWS * HH];
__device__ float g_er[MROWS * HH];
__device__ int   g_rowstart[NN + 1];
__device__ int   g_csr_src[EE];
__device__ float g_part[NPART * HD];
__device__ float g_partsq[NPART * HD];
__device__ float g_scale[HD];
__device__ float g_shift[HD];
__device__ __nv_bfloat16 g_wthi[3 * HD * HD];
__device__ __nv_bfloat16 g_wtlo[3 * HD * HD];

__device__ __forceinline__ uint32_t s2u(const void* p) {
    uint32_t a;
    asm("{ .reg .u64 t; cvta.to.shared.u64 t, %1; cvt.u32.u64 %0, t; }" : "=r"(a) : "l"(p));
    return a;
}
__device__ __forceinline__ void ldsm4(uint32_t* r, uint32_t a) {
    asm volatile("ldmatrix.sync.aligned.m8n8.x4.shared.b16 {%0,%1,%2,%3}, [%4];"
                 : "=r"(r[0]), "=r"(r[1]), "=r"(r[2]), "=r"(r[3]) : "r"(a));
}
__device__ __forceinline__ void mma16816(float* c, const uint32_t* a, const uint32_t* b) {
    asm volatile(
        "mma.sync.aligned.m16n8k16.row.col.f32.bf16.bf16.f32 "
        "{%0,%1,%2,%3}, {%4,%5,%6,%7}, {%8,%9}, {%0,%1,%2,%3};"
        : "+f"(c[0]), "+f"(c[1]), "+f"(c[2]), "+f"(c[3])
        : "r"(a[0]), "r"(a[1]), "r"(a[2]), "r"(a[3]), "r"(b[0]), "r"(b[1]));
}

// ---------------- CSR build (single block) ----------------
__global__ __launch_bounds__(1024) void k_csr(const int* __restrict__ src,
                                              const int* __restrict__ dst) {
    __shared__ int s_start[NN];
    __shared__ int s_tmp[1024];
    const int t = threadIdx.x;

    for (int i = t; i < NN; i += 1024) s_start[i] = 0;
    __syncthreads();
    for (int e = t; e < EE; e += 1024) atomicAdd(&s_start[dst[e]], 1);
    __syncthreads();

    int carry = 0;
    for (int base = 0; base < NN; base += 1024) {
        int v = (base + t < NN) ? s_start[base + t] : 0;
        s_tmp[t] = v;
        __syncthreads();
        for (int off = 1; off < 1024; off <<= 1) {
            int x = (t >= off) ? s_tmp[t - off] : 0;
            __syncthreads();
            s_tmp[t] += x;
            __syncthreads();
        }
        int incl = s_tmp[t];
        int tot = s_tmp[1023];
        __syncthreads();
        if (base + t < NN) {
            int ex = carry + incl - v;
            s_start[base + t] = ex;
            g_rowstart[base + t] = ex;
        }
        carry += tot;
    }
    if (t == 0) g_rowstart[NN] = carry;
    __syncthreads();

    for (int e = t; e < EE; e += 1024) {
        int v = dst[e];
        int p = atomicAdd(&s_start[v], 1);
        g_csr_src[p] = src[e];
    }
}

__global__ void k_copyx(const float* __restrict__ xx) {
    int i = blockIdx.x * blockDim.x + threadIdx.x;
    if (i < MROWS * IND) g_x[i] = xx[i];
}

// ---------------- W transpose + bf16 split ----------------
__global__ void k_wprep(const float* __restrict__ W1, const float* __restrict__ W2,
                        const float* __restrict__ W3) {
    int k = blockIdx.x;
    int l = blockIdx.y;
    int n = threadIdx.x;
    const float* W = (l == 0) ? W1 : (l == 1) ? W2 : W3;
    float v = W[k * HD + n];
    __nv_bfloat16 h = __float2bfloat16(v);
    float lo = v - __bfloat162float(h);
    int o = l * HD * HD + n * HD + k;
    g_wthi[o] = h;
    g_wtlo[o] = __float2bfloat16(lo);
}

// ---------------- layer-0 FC ----------------
__global__ __launch_bounds__(256) void k_fc0(const float* __restrict__ W,
                                             const float* __restrict__ al,
                                             const float* __restrict__ ar) {
    __shared__ float sW[IND * HD];
    __shared__ float sx[FC_ROWS * IND];
    __shared__ float pel[FC_ROWS][8], per_[FC_ROWS][8];
    const int t = threadIdx.x;
    const int m0 = blockIdx.x * FC_ROWS;
    const int w = t >> 5, lane = t & 31;

    for (int i = t; i < IND * HD; i += 256) sW[i] = W[i];
    for (int i = t; i < FC_ROWS * IND; i += 256) sx[i] = g_x[m0 * IND + i];
    __syncthreads();

    const float alv = __ldg(&al[t]);
    const float arv = __ldg(&ar[t]);

#pragma unroll
    for (int r = 0; r < FC_ROWS; r++) {
        float acc = 0.f;
#pragma unroll
        for (int k = 0; k < IND; k++) acc = fmaf(sx[r * IND + k], sW[k * HD + t], acc);
        g_h[(size_t)(m0 + r) * HD + t] = acc;
        float ve = acc * alv, vr = acc * arv;
#pragma unroll
        for (int off = 16; off; off >>= 1) {
            ve += __shfl_xor_sync(0xffffffffu, ve, off);
            vr += __shfl_xor_sync(0xffffffffu, vr, off);
        }
        if (lane == 0) { pel[r][w] = ve; per_[r][w] = vr; }
    }
    __syncthreads();
    if (t < FC_ROWS * HH) {
        int r = t >> 2, h = t & 3;
        g_el[(m0 + r) * HH + h] = pel[r][2 * h] + pel[r][2 * h + 1];
        g_er[(m0 + r) * HH + h] = per_[r][2 * h] + per_[r][2 * h + 1];
    }
}

// ---------------- HMMA GEMM (B resident, A double-buffered, fused BN+el/er) ----------------
__global__ __launch_bounds__(256) void k_gemm(int wsel, const float* __restrict__ al,
                                              const float* __restrict__ ar) {
    extern __shared__ char sm[];
    __shared__ float s_sc[HD], s_sh[HD];
    __nv_bfloat16* Bhi = (__nv_bfloat16*)sm;
    __nv_bfloat16* Blo = Bhi + 128 * BSTR;
    __nv_bfloat16* Abase = Blo + 128 * BSTR;
    const uint32_t uBhi = s2u(Bhi), uBlo = s2u(Blo);
    const uint32_t uA = s2u(Abase);

    const int t = threadIdx.x;
    const int lane = t & 31, warp = t >> 5;
    const int bx = blockIdx.x, by = blockIdx.y;
    const int row0 = by * TM, col0 = bx * TN;
    const int warp_m = (warp >> 1) * 32;
    const int warp_n = (warp & 1) * 64;
    const int head = bx * 2 + (warp & 1);

    s_sc[t] = g_scale[t];
    s_sh[t] = g_shift[t];

    const __nv_bfloat16* wh = g_wthi + wsel * HD * HD;
    const __nv_bfloat16* wl = g_wtlo + wsel * HD * HD;

    {
        int n = t >> 1, kh = (t & 1) * 128;
        int gn = col0 + n;
        const uint4* ph = (const uint4*)&wh[gn * HD + kh];
        const uint4* pl = (const uint4*)&wl[gn * HD + kh];
#pragma unroll
        for (int q = 0; q < 16; q++) {
            *(uint4*)&Bhi[n * BSTR + kh + 8 * q] = __ldg(&ph[q]);
            *(uint4*)&Blo[n * BSTR + kh + 8 * q] = __ldg(&pl[q]);
        }
    }

    float c[2][8][4];
#pragma unroll
    for (int i = 0; i < 2; i++)
#pragma unroll
        for (int j = 0; j < 8; j++)
#pragma unroll
            for (int q = 0; q < 4; q++) c[i][j][q] = 0.f;

    const int a_row = ((lane >> 3) & 1) * 8 + (lane & 7);
    const int a_kof = (lane >> 4) * 8;
    const int b_nsel = (lane >> 4) & 1;
    const int b_ksel = (lane >> 3) & 1;
    const int b_row = (lane & 7);

    auto convA = [&](int ch, int bf) {
        __nv_bfloat16* Ahi = Abase + bf * 2 * 128 * ASTR;
        __nv_bfloat16* Alo = Ahi + 128 * ASTR;
        const int k0 = ch * KC;
        int r = t >> 1, c0i = (t & 1) * 32;
        int grow = row0 + r;
        float x[32];
        if (grow < MROWS) {
            const float4* p = (const float4*)&g_hout[(size_t)grow * HD + k0 + c0i];
#pragma unroll
            for (int q = 0; q < 8; q++) {
                float4 v = p[q];
                x[4 * q + 0] = v.x; x[4 * q + 1] = v.y; x[4 * q + 2] = v.z; x[4 * q + 3] = v.w;
            }
        } else {
#pragma unroll
            for (int j = 0; j < 32; j++) x[j] = 0.f;
        }
#pragma unroll
        for (int j = 0; j < 32; j++) {
            float v = fmaf(x[j], s_sc[k0 + c0i + j], s_sh[k0 + c0i + j]);
            x[j] = v > 0.f ? v : 0.01f * v;
        }
#pragma unroll
        for (int q = 0; q < 4; q++) {
            union { __nv_bfloat16 b[8]; uint4 u; } uh, ul;
#pragma unroll
            for (int j = 0; j < 8; j++) {
                float xv = x[8 * q + j];
                __nv_bfloat16 h = __float2bfloat16(xv);
                uh.b[j] = h;
                ul.b[j] = __float2bfloat16(xv - __bfloat162float(h));
            }
            *(uint4*)&Ahi[r * ASTR + c0i + 8 * q] = uh.u;
            *(uint4*)&Alo[r * ASTR + c0i + 8 * q] = ul.u;
        }
    };

    convA(0, 0);
    __syncthreads();

    for (int ch = 0; ch < 4; ch++) {
        const int bf = ch & 1;
        const uint32_t uAhi = uA + (uint32_t)(bf * 2 * 128 * ASTR * 2);
        const uint32_t uAlo = uAhi + 128 * ASTR * 2;
#pragma unroll
        for (int ks = 0; ks < 4; ks++) {
            const int kg = ch * 4 + ks;
            uint32_t afh[2][4], afl[2][4];
            uint32_t bfh[8][2], bfl[8][2];
#pragma unroll
            for (int mt = 0; mt < 2; mt++) {
                uint32_t off = (uint32_t)(((warp_m + mt * 16 + a_row) * ASTR + 16 * ks + a_kof) * 2);
                ldsm4(afh[mt], uAhi + off);
                ldsm4(afl[mt], uAlo + off);
            }
#pragma unroll
            for (int p = 0; p < 4; p++) {
                uint32_t off = (uint32_t)(((warp_n + (2 * p + b_nsel) * 8 + b_row) * BSTR + 16 * kg + 8 * b_ksel) * 2);
                uint32_t r4[4];
                ldsm4(r4, uBhi + off);
                bfh[2 * p][0] = r4[0]; bfh[2 * p][1] = r4[1];
                bfh[2 * p + 1][0] = r4[2]; bfh[2 * p + 1][1] = r4[3];
                ldsm4(r4, uBlo + off);
                bfl[2 * p][0] = r4[0]; bfl[2 * p][1] = r4[1];
                bfl[2 * p + 1][0] = r4[2]; bfl[2 * p + 1][1] = r4[3];
            }
#pragma unroll
            for (int mt = 0; mt < 2; mt++)
#pragma unroll
                for (int nt = 0; nt < 8; nt++) {
                    mma16816(c[mt][nt], afh[mt], bfh[nt]);
                    mma16816(c[mt][nt], afh[mt], bfl[nt]);
                    mma16816(c[mt][nt], afl[mt], bfh[nt]);
                }
        }
        if (ch < 3) {
            convA(ch + 1, (ch + 1) & 1);
            __syncthreads();
        }
    }

    float elacc[2][2] = {{0.f, 0.f}, {0.f, 0.f}};
    float eracc[2][2] = {{0.f, 0.f}, {0.f, 0.f}};
    const int qn = 2 * (lane & 3);
    const int g = lane >> 2;
#pragma unroll
    for (int mt = 0; mt < 2; mt++) {
#pragma unroll
        for (int nt = 0; nt < 8; nt++) {
            float v0 = c[mt][nt][0], v1 = c[mt][nt][1];
            float v2 = c[mt][nt][2], v3 = c[mt][nt][3];
            int cih = nt * 8 + qn;
            float a0 = __ldg(&al[head * DD + cih]), a1 = __ldg(&al[head * DD + cih + 1]);
            float r0 = __ldg(&ar[head * DD + cih]), r1 = __ldg(&ar[head * DD + cih + 1]);
            elacc[mt][0] = fmaf(v0, a0, fmaf(v1, a1, elacc[mt][0]));
            elacc[mt][1] = fmaf(v2, a0, fmaf(v3, a1, elacc[mt][1]));
            eracc[mt][0] = fmaf(v0, r0, fmaf(v1, r1, eracc[mt][0]));
            eracc[mt][1] = fmaf(v2, r0, fmaf(v3, r1, eracc[mt][1]));
            int gcol = col0 + warp_n + cih;
            int grow0 = row0 + warp_m + mt * 16 + g;
            int grow1 = grow0 + 8;
            if (grow0 < MROWS) *(float2*)&g_h[(size_t)grow0 * HD + gcol] = make_float2(v0, v1);
            if (grow1 < MROWS) *(float2*)&g_h[(size_t)grow1 * HD + gcol] = make_float2(v2, v3);
        }
    }
#pragma unroll
    for (int mt = 0; mt < 2; mt++)
#pragma unroll
        for (int half = 0; half < 2; half++) {
            float e = elacc[mt][half], r = eracc[mt][half];
            e += __shfl_xor_sync(0xffffffffu, e, 1);
            e += __shfl_xor_sync(0xffffffffu, e, 2);
            r += __shfl_xor_sync(0xffffffffu, r, 1);
            r += __shfl_xor_sync(0xffffffffu, r, 2);
            int row = row0 + warp_m + mt * 16 + half * 8 + g;
            if ((lane & 3) == 0 && row < MROWS) {
                g_el[row * HH + head] = e;
                g_er[row * HH + head] = r;
            }
        }
}

// ---------------- edge softmax + aggregation (vectorized) + fused BN partials ----------------
__global__ __launch_bounds__(256) void k_agg() {
    const int bn = blockIdx.x;
    const int b  = bn / NN;
    const int v  = bn - b * NN;
    const int t  = threadIdx.x;

    const int e0 = g_rowstart[v];
    const int deg = g_rowstart[v + 1] - e0;
    float* outp = g_hout + (size_t)bn * HD;
    if (deg == 0) { outp[t] = 0.f; return; }

    __shared__ float sh_er[HH];
    __shared__ float sh_m[HH], sh_is[HH];
    __shared__ float sh_red[8][HH];
    __shared__ int   sh_src[256];
    __shared__ float sh_a[HH][256];
    __shared__ float4 sh_acc[3][64];

    if (t < HH) sh_er[t] = g_er[bn * HH + t];
    __syncthreads();

    const int lane = t & 31, warp = t >> 5;
    const int th_h  = t & 3;       // head for phases A/B/alpha
    const int th_i0 = t >> 2;      // edge offset (64 edges per iteration)
    const int rowbase = b * NN;
    const float erv = sh_er[th_h];

    // ---- Phase A: per-head max over edges ----
    float mv = -INFINITY;
    for (int i = th_i0; i < deg; i += 64) {
        int s = g_csr_src[e0 + i];
        float e = g_el[(rowbase + s) * HH + th_h] + erv;
        e = e > 0.f ? e : 0.2f * e;
        mv = fmaxf(mv, e);
    }
    mv = fmaxf(mv, __shfl_xor_sync(0xffffffffu, mv, 4));
    mv = fmaxf(mv, __shfl_xor_sync(0xffffffffu, mv, 8));
    mv = fmaxf(mv, __shfl_xor_sync(0xffffffffu, mv, 16));
    if (lane < HH) sh_red[warp][lane] = mv;
    __syncthreads();
    if (t < HH) {
        float m2 = sh_red[0][t];
#pragma unroll
        for (int wrp = 1; wrp < 8; wrp++) m2 = fmaxf(m2, sh_red[wrp][t]);
        sh_m[t] = m2;
    }
    __syncthreads();
    const float m = sh_m[th_h];

    // ---- Phase B: per-head sum of exp ----
    float sum = 0.f;
    for (int i = th_i0; i < deg; i += 64) {
        int s = g_csr_src[e0 + i];
        float e = g_el[(rowbase + s) * HH + th_h] + erv;
        e = e > 0.f ? e : 0.2f * e;
        sum += __expf(e - m);
    }
    sum += __shfl_xor_sync(0xffffffffu, sum, 4);
    sum += __shfl_xor_sync(0xffffffffu, sum, 8);
    sum += __shfl_xor_sync(0xffffffffu, sum, 16);
    if (lane < HH) sh_red[warp][lane] = sum;
    __syncthreads();
    if (t < HH) {
        float s2 = 0.f;
#pragma unroll
        for (int wrp = 0; wrp < 8; wrp++) s2 += sh_red[wrp][t];
        sh_is[t] = 1.f / s2;
    }
    __syncthreads();
    const float inv = sh_is[th_h];

    // ---- Phase C: gather, 4 cols/thread (float4), 4 edge slots ----
    const int c4 = (t & 63) * 4;
    const int hc = (t & 63) >> 4;       // head of this column group
    const int eslot = t >> 6;
    const float* hb = g_h + (((size_t)rowbase) << 8) + c4;
    float4 acc = make_float4(0.f, 0.f, 0.f, 0.f);

    for (int base = 0; base < deg; base += 256) {
        int len = min(256, deg - base);
        for (int i = th_i0; i < len; i += 64) {
            int s = g_csr_src[e0 + base + i];
            if (th_h == 0) sh_src[i] = s;
            float e = g_el[(rowbase + s) * HH + th_h] + erv;
            e = e > 0.f ? e : 0.2f * e;
            sh_a[th_h][i] = __expf(e - m) * inv;
        }
        __syncthreads();
        int i = eslot;
        for (; i + 8 <= len; i += 8) {
            int s0 = sh_src[i], s1 = sh_src[i + 4];
            float w0 = sh_a[hc][i], w1 = sh_a[hc][i + 4];
            float4 h0 = *(const float4*)(hb + ((size_t)s0 << 8));
            float4 h1 = *(const float4*)(hb + ((size_t)s1 << 8));
            acc.x = fmaf(w0, h0.x, acc.x); acc.y = fmaf(w0, h0.y, acc.y);
            acc.z = fmaf(w0, h0.z, acc.z); acc.w = fmaf(w0, h0.w, acc.w);
            acc.x = fmaf(w1, h1.x, acc.x); acc.y = fmaf(w1, h1.y, acc.y);
            acc.z = fmaf(w1, h1.z, acc.z); acc.w = fmaf(w1, h1.w, acc.w);
        }
        for (; i < len; i += 4) {
            int s0 = sh_src[i];
            float w0 = sh_a[hc][i];
            float4 h0 = *(const float4*)(hb + ((size_t)s0 << 8));
            acc.x = fmaf(w0, h0.x, acc.x); acc.y = fmaf(w0, h0.y, acc.y);
            acc.z = fmaf(w0, h0.z, acc.z); acc.w = fmaf(w0, h0.w, acc.w);
        }
        __syncthreads();
    }

    // ---- reduce across the 4 edge slots ----
    if (eslot) sh_acc[eslot - 1][t & 63] = acc;
    __syncthreads();
    if (eslot == 0) {
        float4 a1 = sh_acc[0][t], a2 = sh_acc[1][t], a3 = sh_acc[2][t];
        acc.x += (a1.x + a2.x) + a3.x;
        acc.y += (a1.y + a2.y) + a3.y;
        acc.z += (a1.z + a2.z) + a3.z;
        acc.w += (a1.w + a2.w) + a3.w;
        *(float4*)(outp + c4) = acc;
        int slot = (bn & (NPART - 1)) * HD + c4;
        atomicAdd(&g_part[slot + 0], acc.x);
        atomicAdd(&g_part[slot + 1], acc.y);
        atomicAdd(&g_part[slot + 2], acc.z);
        atomicAdd(&g_part[slot + 3], acc.w);
        atomicAdd(&g_partsq[slot + 0], acc.x * acc.x);
        atomicAdd(&g_partsq[slot + 1], acc.y * acc.y);
        atomicAdd(&g_partsq[slot + 2], acc.z * acc.z);
        atomicAdd(&g_partsq[slot + 3], acc.w * acc.w);
    }
}

// ---------------- BatchNorm finalize ----------------
__global__ void k_bnfin(const float* __restrict__ gamma, const float* __restrict__ beta) {
    int c = threadIdx.x;
    float s = 0.f, sq = 0.f;
#pragma unroll
    for (int i = 0; i < NPART; i++) {
        s  += g_part[i * HD + c];
        sq += g_partsq[i * HD + c];
        g_part[i * HD + c] = 0.f;
        g_partsq[i * HD + c] = 0.f;
    }
    float inv = 1.f / (float)MROWS;
    float mu = s * inv;
    float var = sq * inv - mu * mu;
    float sc = gamma[c] * rsqrtf(var + EPSBN);
    g_scale[c] = sc;
    g_shift[c] = beta[c] - mu * sc;
}

// ---------------- output projection + autoregressive shift ----------------
__global__ void k_proj(const float* __restrict__ Wo, const float* __restrict__ bo,
                       float* __restrict__ out, int step) {
    int bn = blockIdx.x;
    int w = threadIdx.x >> 5, lane = threadIdx.x & 31;
    __shared__ float sval[OUTD];
    const float* hp = g_hout + (size_t)bn * HD;
    float sum = 0.f;
#pragma unroll
    for (int k = lane; k < HD; k += 32) {
        float xv = fmaf(hp[k], g_scale[k], g_shift[k]);
        xv = xv > 0.f ? xv : 0.01f * xv;
        sum = fmaf(xv, Wo[k * OUTD + w], sum);
    }
#pragma unroll
    for (int off = 16; off; off >>= 1) sum += __shfl_xor_sync(0xffffffffu, sum, off);
    if (lane == 0) sval[w] = sum + bo[w];

    float keep = 0.f;
    if (threadIdx.x < IND - OUTD) keep = g_x[bn * IND + threadIdx.x + OUTD];
    __syncthreads();
    if (threadIdx.x < IND - OUTD) g_x[bn * IND + threadIdx.x] = keep;
    else if (threadIdx.x < IND) g_x[bn * IND + threadIdx.x] = sval[threadIdx.x - (IND - OUTD)];
    if (threadIdx.x < OUTD) out[(bn * TSTEPS + step) * OUTD + threadIdx.x] = sval[threadIdx.x];
}

// ---------------- launcher ----------------
extern "C" void kernel_launch(void* const* d_in, const int* in_sizes, int n_in,
                              void* d_out, int out_size) {
    const float* xx  = (const float*)d_in[0];
    const int*   src = (const int*)d_in[1];
    const int*   dst = (const int*)d_in[2];
    const float *W[4], *al[4], *ar[4], *gamma[4], *beta[4];
    for (int l = 0; l < 4; l++) {
        W[l]     = (const float*)d_in[3 + 5 * l];
        al[l]    = (const float*)d_in[4 + 5 * l];
        ar[l]    = (const float*)d_in[5 + 5 * l];
        gamma[l] = (const float*)d_in[6 + 5 * l];
        beta[l]  = (const float*)d_in[7 + 5 * l];
    }
    const float* W_out = (const float*)d_in[23];
    const float* b_out = (const float*)d_in[24];
    float* out = (float*)d_out;

    cudaFuncSetAttribute(k_gemm, cudaFuncAttributeMaxDynamicSharedMemorySize, GSM_BYTES);

    dim3 ggrid(HD / TN, (MROWS + TM - 1) / TM);

    // launch #4 = k_gemm (dummy; outputs fully overwritten by k_fc0) so the
    // profiler's fixed capture slot shows the GEMM roofline next round.
    k_csr<<<1, 1024>>>(src, dst);                                // 1
    k_copyx<<<(MROWS * IND + 255) / 256, 256>>>(xx);             // 2
    k_wprep<<<dim3(HD, 3), HD>>>(W[1], W[2], W[3]);              // 3
    k_gemm<<<ggrid, 256, GSM_BYTES>>>(0, al[1], ar[1]);          // 4  <-- profiled
    k_fc0<<<MROWS / FC_ROWS, 256>>>(W[0], al[0], ar[0]);         // 5

    for (int step = 0; step < TSTEPS; step++) {
        for (int l = 0; l < 4; l++) {
            if (l > 0)
                k_gemm<<<ggrid, 256, GSM_BYTES>>>(l - 1, al[l], ar[l]);
            else if (step > 0)
                k_fc0<<<MROWS / FC_ROWS, 256>>>(W[0], al[0], ar[0]);
            k_agg<<<MROWS, 256>>>();
            k_bnfin<<<1, HD>>>(gamma[l], beta[l]);
        }
        k_proj<<<MROWS, 96>>>(W_out, b_out, out, step);
    }
}

// round 7
// speedup vs baseline: 1.1418x; 1.1258x over previous
#include <cuda_runtime.h>
#include <cuda_bf16.h>
#include <math.h>
#include <stdint.h>

// ---------------- problem constants ----------------
#define BB 8
#define NN 5000
#define EE 80000
#define IND 30
#define HH 4
#define DD 64
#define HD 256
#define OUTD 3
#define TSTEPS 5
#define EPSBN 1e-5f
#define MROWS (BB*NN)   // 40000

// GEMM tiling
#define TM 128
#define TN 128
#define KC 64
#define ASTR 72
#define BSTR 264
#define NPART 64
#define FC_ROWS 16

#define B_BYTES (128 * BSTR * 2)
#define A_BYTES (128 * ASTR * 2)
#define GSM_BYTES (2 * B_BYTES + 4 * A_BYTES)

// ---------------- device scratch ----------------
__device__ float g_x[MROWS * IND];
__device__ float g_h[MROWS * HD];
__device__ float g_hout[MROWS * HD];
__device__ float g_el[MROWS * HH];
__device__ float g_er[MROWS * HH];
__device__ int   g_rowstart[NN + 1];
__device__ int   g_csr_src[EE];
__device__ float g_part[NPART * HD];
__device__ float g_partsq[NPART * HD];
__device__ float g_scale[HD];
__device__ float g_shift[HD];
__device__ __nv_bfloat16 g_wthi[3 * HD * HD];
__device__ __nv_bfloat16 g_wtlo[3 * HD * HD];

__device__ __forceinline__ uint32_t s2u(const void* p) {
    uint32_t a;
    asm("{ .reg .u64 t; cvta.to.shared.u64 t, %1; cvt.u32.u64 %0, t; }" : "=r"(a) : "l"(p));
    return a;
}
__device__ __forceinline__ void ldsm4(uint32_t* r, uint32_t a) {
    asm volatile("ldmatrix.sync.aligned.m8n8.x4.shared.b16 {%0,%1,%2,%3}, [%4];"
                 : "=r"(r[0]), "=r"(r[1]), "=r"(r[2]), "=r"(r[3]) : "r"(a));
}
__device__ __forceinline__ void mma16816(float* c, const uint32_t* a, const uint32_t* b) {
    asm volatile(
        "mma.sync.aligned.m16n8k16.row.col.f32.bf16.bf16.f32 "
        "{%0,%1,%2,%3}, {%4,%5,%6,%7}, {%8,%9}, {%0,%1,%2,%3};"
        : "+f"(c[0]), "+f"(c[1]), "+f"(c[2]), "+f"(c[3])
        : "r"(a[0]), "r"(a[1]), "r"(a[2]), "r"(a[3]), "r"(b[0]), "r"(b[1]));
}

// ---------------- CSR build (single block) ----------------
__global__ __launch_bounds__(1024) void k_csr(const int* __restrict__ src,
                                              const int* __restrict__ dst) {
    __shared__ int s_start[NN];
    __shared__ int s_tmp[1024];
    const int t = threadIdx.x;

    for (int i = t; i < NN; i += 1024) s_start[i] = 0;
    __syncthreads();
    for (int e = t; e < EE; e += 1024) atomicAdd(&s_start[dst[e]], 1);
    __syncthreads();

    int carry = 0;
    for (int base = 0; base < NN; base += 1024) {
        int v = (base + t < NN) ? s_start[base + t] : 0;
        s_tmp[t] = v;
        __syncthreads();
        for (int off = 1; off < 1024; off <<= 1) {
            int x = (t >= off) ? s_tmp[t - off] : 0;
            __syncthreads();
            s_tmp[t] += x;
            __syncthreads();
        }
        int incl = s_tmp[t];
        int tot = s_tmp[1023];
        __syncthreads();
        if (base + t < NN) {
            int ex = carry + incl - v;
            s_start[base + t] = ex;
            g_rowstart[base + t] = ex;
        }
        carry += tot;
    }
    if (t == 0) g_rowstart[NN] = carry;
    __syncthreads();

    for (int e = t; e < EE; e += 1024) {
        int v = dst[e];
        int p = atomicAdd(&s_start[v], 1);
        g_csr_src[p] = src[e];
    }
}

__global__ void k_copyx(const float* __restrict__ xx) {
    int i = blockIdx.x * blockDim.x + threadIdx.x;
    if (i < MROWS * IND) g_x[i] = xx[i];
}

// ---------------- W transpose + bf16 split ----------------
__global__ void k_wprep(const float* __restrict__ W1, const float* __restrict__ W2,
                        const float* __restrict__ W3) {
    int k = blockIdx.x;
    int l = blockIdx.y;
    int n = threadIdx.x;
    const float* W = (l == 0) ? W1 : (l == 1) ? W2 : W3;
    float v = W[k * HD + n];
    __nv_bfloat16 h = __float2bfloat16(v);
    float lo = v - __bfloat162float(h);
    int o = l * HD * HD + n * HD + k;
    g_wthi[o] = h;
    g_wtlo[o] = __float2bfloat16(lo);
}

// ---------------- layer-0 FC ----------------
__global__ __launch_bounds__(256) void k_fc0(const float* __restrict__ W,
                                             const float* __restrict__ al,
                                             const float* __restrict__ ar) {
    __shared__ float sW[IND * HD];
    __shared__ float sx[FC_ROWS * IND];
    __shared__ float pel[FC_ROWS][8], per_[FC_ROWS][8];
    const int t = threadIdx.x;
    const int m0 = blockIdx.x * FC_ROWS;
    const int w = t >> 5, lane = t & 31;

    for (int i = t; i < IND * HD; i += 256) sW[i] = W[i];
    for (int i = t; i < FC_ROWS * IND; i += 256) sx[i] = g_x[m0 * IND + i];
    __syncthreads();

    const float alv = __ldg(&al[t]);
    const float arv = __ldg(&ar[t]);

#pragma unroll
    for (int r = 0; r < FC_ROWS; r++) {
        float acc = 0.f;
#pragma unroll
        for (int k = 0; k < IND; k++) acc = fmaf(sx[r * IND + k], sW[k * HD + t], acc);
        g_h[(size_t)(m0 + r) * HD + t] = acc;
        float ve = acc * alv, vr = acc * arv;
#pragma unroll
        for (int off = 16; off; off >>= 1) {
            ve += __shfl_xor_sync(0xffffffffu, ve, off);
            vr += __shfl_xor_sync(0xffffffffu, vr, off);
        }
        if (lane == 0) { pel[r][w] = ve; per_[r][w] = vr; }
    }
    __syncthreads();
    if (t < FC_ROWS * HH) {
        int r = t >> 2, h = t & 3;
        g_el[(m0 + r) * HH + h] = pel[r][2 * h] + pel[r][2 * h + 1];
        g_er[(m0 + r) * HH + h] = per_[r][2 * h] + per_[r][2 * h + 1];
    }
}

// ---------------- HMMA GEMM: 512 threads, warp tile 32x32 ----------------
__global__ __launch_bounds__(512) void k_gemm(int wsel, const float* __restrict__ al,
                                              const float* __restrict__ ar) {
    extern __shared__ char sm[];
    __shared__ float s_sc[HD], s_sh[HD];
    __shared__ float sh_e[2][128][2][2];    // [el/er][row][head2][col-half]
    __nv_bfloat16* Bhi = (__nv_bfloat16*)sm;
    __nv_bfloat16* Blo = Bhi + 128 * BSTR;
    __nv_bfloat16* Abase = Blo + 128 * BSTR;
    const uint32_t uBhi = s2u(Bhi), uBlo = s2u(Blo);
    const uint32_t uA = s2u(Abase);

    const int t = threadIdx.x;
    const int lane = t & 31, warp = t >> 5;       // 16 warps
    const int bx = blockIdx.x, by = blockIdx.y;
    const int row0 = by * TM, col0 = bx * TN;
    const int warp_m = (warp >> 2) * 32;
    const int warp_n = (warp & 3) * 32;
    const int head2 = (warp & 3) >> 1;            // head within CTA (0/1)
    const int halfid = warp & 1;                  // which 32-col half of the head
    const int head = bx * 2 + head2;

    if (t < HD) { s_sc[t] = g_scale[t]; s_sh[t] = g_shift[t]; }

    const __nv_bfloat16* wh = g_wthi + wsel * HD * HD;
    const __nv_bfloat16* wl = g_wtlo + wsel * HD * HD;

    // ---- load full B (128 x 256, hi+lo) ----
    {
        int n = t >> 2, kq = (t & 3) * 64;
        int gn = col0 + n;
        const uint4* ph = (const uint4*)&wh[gn * HD + kq];
        const uint4* pl = (const uint4*)&wl[gn * HD + kq];
#pragma unroll
        for (int q = 0; q < 8; q++) {
            *(uint4*)&Bhi[n * BSTR + kq + 8 * q] = __ldg(&ph[q]);
            *(uint4*)&Blo[n * BSTR + kq + 8 * q] = __ldg(&pl[q]);
        }
    }

    float c[2][4][4];
#pragma unroll
    for (int i = 0; i < 2; i++)
#pragma unroll
        for (int j = 0; j < 4; j++)
#pragma unroll
            for (int q = 0; q < 4; q++) c[i][j][q] = 0.f;

    const int a_row = ((lane >> 3) & 1) * 8 + (lane & 7);
    const int a_kof = (lane >> 4) * 8;
    const int b_nsel = (lane >> 4) & 1;
    const int b_ksel = (lane >> 3) & 1;
    const int b_row = (lane & 7);

    auto convA = [&](int ch, int bf) {
        __nv_bfloat16* Ahi = Abase + bf * 2 * 128 * ASTR;
        __nv_bfloat16* Alo = Ahi + 128 * ASTR;
        const int k0 = ch * KC;
        int r = t >> 2, c0i = (t & 3) * 16;
        int grow = row0 + r;
        float x[16];
        if (grow < MROWS) {
            const float4* p = (const float4*)&g_hout[(size_t)grow * HD + k0 + c0i];
#pragma unroll
            for (int q = 0; q < 4; q++) {
                float4 v = p[q];
                x[4 * q + 0] = v.x; x[4 * q + 1] = v.y; x[4 * q + 2] = v.z; x[4 * q + 3] = v.w;
            }
        } else {
#pragma unroll
            for (int j = 0; j < 16; j++) x[j] = 0.f;
        }
#pragma unroll
        for (int j = 0; j < 16; j++) {
            float v = fmaf(x[j], s_sc[k0 + c0i + j], s_sh[k0 + c0i + j]);
            x[j] = v > 0.f ? v : 0.01f * v;
        }
#pragma unroll
        for (int q = 0; q < 2; q++) {
            union { __nv_bfloat16 b[8]; uint4 u; } uh, ul;
#pragma unroll
            for (int j = 0; j < 8; j++) {
                float xv = x[8 * q + j];
                __nv_bfloat16 h = __float2bfloat16(xv);
                uh.b[j] = h;
                ul.b[j] = __float2bfloat16(xv - __bfloat162float(h));
            }
            *(uint4*)&Ahi[r * ASTR + c0i + 8 * q] = uh.u;
            *(uint4*)&Alo[r * ASTR + c0i + 8 * q] = ul.u;
        }
    };

    convA(0, 0);
    __syncthreads();

    for (int ch = 0; ch < 4; ch++) {
        const int bf = ch & 1;
        const uint32_t uAhi = uA + (uint32_t)(bf * 2 * 128 * ASTR * 2);
        const uint32_t uAlo = uAhi + 128 * ASTR * 2;
#pragma unroll
        for (int ks = 0; ks < 4; ks++) {
            const int kg = ch * 4 + ks;
            uint32_t afh[2][4], afl[2][4];
            uint32_t bfh[4][2], bfl[4][2];
#pragma unroll
            for (int mt = 0; mt < 2; mt++) {
                uint32_t off = (uint32_t)(((warp_m + mt * 16 + a_row) * ASTR + 16 * ks + a_kof) * 2);
                ldsm4(afh[mt], uAhi + off);
                ldsm4(afl[mt], uAlo + off);
            }
#pragma unroll
            for (int p = 0; p < 2; p++) {
                uint32_t off = (uint32_t)(((warp_n + (2 * p + b_nsel) * 8 + b_row) * BSTR + 16 * kg + 8 * b_ksel) * 2);
                uint32_t r4[4];
                ldsm4(r4, uBhi + off);
                bfh[2 * p][0] = r4[0]; bfh[2 * p][1] = r4[1];
                bfh[2 * p + 1][0] = r4[2]; bfh[2 * p + 1][1] = r4[3];
                ldsm4(r4, uBlo + off);
                bfl[2 * p][0] = r4[0]; bfl[2 * p][1] = r4[1];
                bfl[2 * p + 1][0] = r4[2]; bfl[2 * p + 1][1] = r4[3];
            }
#pragma unroll
            for (int mt = 0; mt < 2; mt++)
#pragma unroll
                for (int nt = 0; nt < 4; nt++) {
                    mma16816(c[mt][nt], afh[mt], bfh[nt]);
                    mma16816(c[mt][nt], afh[mt], bfl[nt]);
                    mma16816(c[mt][nt], afl[mt], bfh[nt]);
                }
        }
        if (ch < 3) {
            convA(ch + 1, (ch + 1) & 1);
            __syncthreads();
        }
    }

    // ---- epilogue: store D + partial el/er into smem, then combine ----
    float elacc[2][2] = {{0.f, 0.f}, {0.f, 0.f}};
    float eracc[2][2] = {{0.f, 0.f}, {0.f, 0.f}};
    const int qn = 2 * (lane & 3);
    const int g = lane >> 2;
#pragma unroll
    for (int mt = 0; mt < 2; mt++) {
#pragma unroll
        for (int nt = 0; nt < 4; nt++) {
            float v0 = c[mt][nt][0], v1 = c[mt][nt][1];
            float v2 = c[mt][nt][2], v3 = c[mt][nt][3];
            int cih = nt * 8 + qn;                       // 0..31 within warp cols
            int hcol = halfid * 32 + cih;                // 0..63 within head
            float a0 = __ldg(&al[head * DD + hcol]), a1 = __ldg(&al[head * DD + hcol + 1]);
            float r0 = __ldg(&ar[head * DD + hcol]), r1 = __ldg(&ar[head * DD + hcol + 1]);
            elacc[mt][0] = fmaf(v0, a0, fmaf(v1, a1, elacc[mt][0]));
            elacc[mt][1] = fmaf(v2, a0, fmaf(v3, a1, elacc[mt][1]));
            eracc[mt][0] = fmaf(v0, r0, fmaf(v1, r1, eracc[mt][0]));
            eracc[mt][1] = fmaf(v2, r0, fmaf(v3, r1, eracc[mt][1]));
            int gcol = col0 + warp_n + cih;
            int grow0 = row0 + warp_m + mt * 16 + g;
            int grow1 = grow0 + 8;
            if (grow0 < MROWS) *(float2*)&g_h[(size_t)grow0 * HD + gcol] = make_float2(v0, v1);
            if (grow1 < MROWS) *(float2*)&g_h[(size_t)grow1 * HD + gcol] = make_float2(v2, v3);
        }
    }
#pragma unroll
    for (int mt = 0; mt < 2; mt++)
#pragma unroll
        for (int half = 0; half < 2; half++) {
            float e = elacc[mt][half], r = eracc[mt][half];
            e += __shfl_xor_sync(0xffffffffu, e, 1);
            e += __shfl_xor_sync(0xffffffffu, e, 2);
            r += __shfl_xor_sync(0xffffffffu, r, 1);
            r += __shfl_xor_sync(0xffffffffu, r, 2);
            if ((lane & 3) == 0) {
                int rr = warp_m + mt * 16 + half * 8 + g;
                sh_e[0][rr][head2][halfid] = e;
                sh_e[1][rr][head2][halfid] = r;
            }
        }
    __syncthreads();
    if (t < 256) {
        int rr = t & 127, h2 = t >> 7;
        int row = row0 + rr;
        if (row < MROWS) {
            g_el[row * HH + bx * 2 + h2] = sh_e[0][rr][h2][0] + sh_e[0][rr][h2][1];
            g_er[row * HH + bx * 2 + h2] = sh_e[1][rr][h2][0] + sh_e[1][rr][h2][1];
        }
    }
}

// ---------------- edge softmax + aggregation: 4 nodes/block, 64 thr/node ----------------
__global__ __launch_bounds__(256) void k_agg() {
    const int t = threadIdx.x;
    const int nl = t >> 6;                    // node slot 0..3
    const int j  = t & 63;
    const int bn = blockIdx.x * 4 + nl;
    const int b  = bn / NN;
    const int v  = bn - b * NN;
    const int rowbase = b * NN;

    const int e0 = g_rowstart[v];
    const int deg = g_rowstart[v + 1] - e0;

    __shared__ int   sh_src[4][64];
    __shared__ float sh_a[4][64][4];
    __shared__ float red[4][2][4];
    __shared__ int   s_nch;

    if (t == 0) s_nch = 1;
    __syncthreads();
    if (j == 0 && deg > 64) atomicMax(&s_nch, (deg + 63) >> 6);

    const float4 erv = *(const float4*)&g_er[bn * HH];
    const int wp = (t >> 5) & 1;              // warp within node
    const int lane = t & 31;

    // ---- pass 1: max (and cache e + src for deg<=64) ----
    float e0r = 0.f, e1r = 0.f, e2r = 0.f, e3r = 0.f;
    float m0 = -INFINITY, m1 = -INFINITY, m2 = -INFINITY, m3 = -INFINITY;
    for (int i = j; i < deg; i += 64) {
        int s = g_csr_src[e0 + i];
        float4 el4 = *(const float4*)&g_el[(rowbase + s) * HH];
        float a0 = el4.x + erv.x, a1 = el4.y + erv.y, a2 = el4.z + erv.z, a3 = el4.w + erv.w;
        e0r = a0 > 0.f ? a0 : 0.2f * a0;
        e1r = a1 > 0.f ? a1 : 0.2f * a1;
        e2r = a2 > 0.f ? a2 : 0.2f * a2;
        e3r = a3 > 0.f ? a3 : 0.2f * a3;
        m0 = fmaxf(m0, e0r); m1 = fmaxf(m1, e1r);
        m2 = fmaxf(m2, e2r); m3 = fmaxf(m3, e3r);
        if (i == j && j < 64) sh_src[nl][j] = s;
    }
#pragma unroll
    for (int off = 16; off; off >>= 1) {
        m0 = fmaxf(m0, __shfl_xor_sync(0xffffffffu, m0, off));
        m1 = fmaxf(m1, __shfl_xor_sync(0xffffffffu, m1, off));
        m2 = fmaxf(m2, __shfl_xor_sync(0xffffffffu, m2, off));
        m3 = fmaxf(m3, __shfl_xor_sync(0xffffffffu, m3, off));
    }
    if (lane == 0) { red[nl][wp][0] = m0; red[nl][wp][1] = m1; red[nl][wp][2] = m2; red[nl][wp][3] = m3; }
    __syncthreads();
    m0 = fmaxf(red[nl][0][0], red[nl][1][0]);
    m1 = fmaxf(red[nl][0][1], red[nl][1][1]);
    m2 = fmaxf(red[nl][0][2], red[nl][1][2]);
    m3 = fmaxf(red[nl][0][3], red[nl][1][3]);
    const int nch = s_nch;
    __syncthreads();

    // ---- pass 2: sum of exp ----
    float s0 = 0.f, s1 = 0.f, s2 = 0.f, s3 = 0.f;
    float p0 = 0.f, p1 = 0.f, p2 = 0.f, p3 = 0.f;
    if (deg <= 64) {
        if (j < deg) {
            p0 = __expf(e0r - m0); p1 = __expf(e1r - m1);
            p2 = __expf(e2r - m2); p3 = __expf(e3r - m3);
            s0 = p0; s1 = p1; s2 = p2; s3 = p3;
        }
    } else {
        for (int i = j; i < deg; i += 64) {
            int s = g_csr_src[e0 + i];
            float4 el4 = *(const float4*)&g_el[(rowbase + s) * HH];
            float a0 = el4.x + erv.x, a1 = el4.y + erv.y, a2 = el4.z + erv.z, a3 = el4.w + erv.w;
            a0 = a0 > 0.f ? a0 : 0.2f * a0;
            a1 = a1 > 0.f ? a1 : 0.2f * a1;
            a2 = a2 > 0.f ? a2 : 0.2f * a2;
            a3 = a3 > 0.f ? a3 : 0.2f * a3;
            s0 += __expf(a0 - m0); s1 += __expf(a1 - m1);
            s2 += __expf(a2 - m2); s3 += __expf(a3 - m3);
        }
    }
#pragma unroll
    for (int off = 16; off; off >>= 1) {
        s0 += __shfl_xor_sync(0xffffffffu, s0, off);
        s1 += __shfl_xor_sync(0xffffffffu, s1, off);
        s2 += __shfl_xor_sync(0xffffffffu, s2, off);
        s3 += __shfl_xor_sync(0xffffffffu, s3, off);
    }
    if (lane == 0) { red[nl][wp][0] = s0; red[nl][wp][1] = s1; red[nl][wp][2] = s2; red[nl][wp][3] = s3; }
    __syncthreads();
    const float i0 = 1.f / (red[nl][0][0] + red[nl][1][0]);
    const float i1 = 1.f / (red[nl][0][1] + red[nl][1][1]);
    const float i2 = 1.f / (red[nl][0][2] + red[nl][1][2]);
    const float i3 = 1.f / (red[nl][0][3] + red[nl][1][3]);

    if (deg <= 64 && j < deg) {
        sh_a[nl][j][0] = p0 * i0; sh_a[nl][j][1] = p1 * i1;
        sh_a[nl][j][2] = p2 * i2; sh_a[nl][j][3] = p3 * i3;
    }

    // ---- pass 3: gather ----
    const int hc = j >> 4;
    const float* hb = g_h + (((size_t)rowbase) << 8) + j * 4;
    float4 acc = make_float4(0.f, 0.f, 0.f, 0.f);

    for (int ch = 0; ch < nch; ch++) {
        int base = ch * 64;
        if (deg > 64) {
            int i = base + j;
            if (i < deg) {
                int s = g_csr_src[e0 + i];
                sh_src[nl][j] = s;
                float4 el4 = *(const float4*)&g_el[(rowbase + s) * HH];
                float a0 = el4.x + erv.x, a1 = el4.y + erv.y, a2 = el4.z + erv.z, a3 = el4.w + erv.w;
                a0 = a0 > 0.f ? a0 : 0.2f * a0;
                a1 = a1 > 0.f ? a1 : 0.2f * a1;
                a2 = a2 > 0.f ? a2 : 0.2f * a2;
                a3 = a3 > 0.f ? a3 : 0.2f * a3;
                sh_a[nl][j][0] = __expf(a0 - m0) * i0;
                sh_a[nl][j][1] = __expf(a1 - m1) * i1;
                sh_a[nl][j][2] = __expf(a2 - m2) * i2;
                sh_a[nl][j][3] = __expf(a3 - m3) * i3;
            }
        }
        __syncthreads();
        int len = min(64, deg - base);
        int i = 0;
        for (; i + 4 <= len; i += 4) {
            int sa = sh_src[nl][i],     sb = sh_src[nl][i + 1];
            int sc = sh_src[nl][i + 2], sd = sh_src[nl][i + 3];
            float wa = sh_a[nl][i][hc],     wb = sh_a[nl][i + 1][hc];
            float wc = sh_a[nl][i + 2][hc], wd = sh_a[nl][i + 3][hc];
            float4 ha = *(const float4*)(hb + ((size_t)sa << 8));
            float4 hbv = *(const float4*)(hb + ((size_t)sb << 8));
            float4 hcv = *(const float4*)(hb + ((size_t)sc << 8));
            float4 hdv = *(const float4*)(hb + ((size_t)sd << 8));
            acc.x = fmaf(wa, ha.x, acc.x);  acc.y = fmaf(wa, ha.y, acc.y);
            acc.z = fmaf(wa, ha.z, acc.z);  acc.w = fmaf(wa, ha.w, acc.w);
            acc.x = fmaf(wb, hbv.x, acc.x); acc.y = fmaf(wb, hbv.y, acc.y);
            acc.z = fmaf(wb, hbv.z, acc.z); acc.w = fmaf(wb, hbv.w, acc.w);
            acc.x = fmaf(wc, hcv.x, acc.x); acc.y = fmaf(wc, hcv.y, acc.y);
            acc.z = fmaf(wc, hcv.z, acc.z); acc.w = fmaf(wc, hcv.w, acc.w);
            acc.x = fmaf(wd, hdv.x, acc.x); acc.y = fmaf(wd, hdv.y, acc.y);
            acc.z = fmaf(wd, hdv.z, acc.z); acc.w = fmaf(wd, hdv.w, acc.w);
        }
        for (; i < len; i++) {
            int s = sh_src[nl][i];
            float w = sh_a[nl][i][hc];
            float4 hv = *(const float4*)(hb + ((size_t)s << 8));
            acc.x = fmaf(w, hv.x, acc.x); acc.y = fmaf(w, hv.y, acc.y);
            acc.z = fmaf(w, hv.z, acc.z); acc.w = fmaf(w, hv.w, acc.w);
        }
        __syncthreads();
    }

    float* outp = g_hout + (size_t)bn * HD + j * 4;
    *(float4*)outp = acc;
    int slot = (bn & (NPART - 1)) * HD + j * 4;
    atomicAdd(&g_part[slot + 0], acc.x);
    atomicAdd(&g_part[slot + 1], acc.y);
    atomicAdd(&g_part[slot + 2], acc.z);
    atomicAdd(&g_part[slot + 3], acc.w);
    atomicAdd(&g_partsq[slot + 0], acc.x * acc.x);
    atomicAdd(&g_partsq[slot + 1], acc.y * acc.y);
    atomicAdd(&g_partsq[slot + 2], acc.z * acc.z);
    atomicAdd(&g_partsq[slot + 3], acc.w * acc.w);
}

// ---------------- BatchNorm finalize ----------------
__global__ void k_bnfin(const float* __restrict__ gamma, const float* __restrict__ beta) {
    int c = threadIdx.x;
    float s = 0.f, sq = 0.f;
#pragma unroll
    for (int i = 0; i < NPART; i++) {
        s  += g_part[i * HD + c];
        sq += g_partsq[i * HD + c];
        g_part[i * HD + c] = 0.f;
        g_partsq[i * HD + c] = 0.f;
    }
    float inv = 1.f / (float)MROWS;
    float mu = s * inv;
    float var = sq * inv - mu * mu;
    float sc = gamma[c] * rsqrtf(var + EPSBN);
    g_scale[c] = sc;
    g_shift[c] = beta[c] - mu * sc;
}

// ---------------- output projection + autoregressive shift ----------------
__global__ void k_proj(const float* __restrict__ Wo, const float* __restrict__ bo,
                       float* __restrict__ out, int step) {
    int bn = blockIdx.x;
    int w = threadIdx.x >> 5, lane = threadIdx.x & 31;
    __shared__ float sval[OUTD];
    const float* hp = g_hout + (size_t)bn * HD;
    float sum = 0.f;
#pragma unroll
    for (int k = lane; k < HD; k += 32) {
        float xv = fmaf(hp[k], g_scale[k], g_shift[k]);
        xv = xv > 0.f ? xv : 0.01f * xv;
        sum = fmaf(xv, Wo[k * OUTD + w], sum);
    }
#pragma unroll
    for (int off = 16; off; off >>= 1) sum += __shfl_xor_sync(0xffffffffu, sum, off);
    if (lane == 0) sval[w] = sum + bo[w];

    float keep = 0.f;
    if (threadIdx.x < IND - OUTD) keep = g_x[bn * IND + threadIdx.x + OUTD];
    __syncthreads();
    if (threadIdx.x < IND - OUTD) g_x[bn * IND + threadIdx.x] = keep;
    else if (threadIdx.x < IND) g_x[bn * IND + threadIdx.x] = sval[threadIdx.x - (IND - OUTD)];
    if (threadIdx.x < OUTD) out[(bn * TSTEPS + step) * OUTD + threadIdx.x] = sval[threadIdx.x];
}

// ---------------- launcher ----------------
extern "C" void kernel_launch(void* const* d_in, const int* in_sizes, int n_in,
                              void* d_out, int out_size) {
    const float* xx  = (const float*)d_in[0];
    const int*   src = (const int*)d_in[1];
    const int*   dst = (const int*)d_in[2];
    const float *W[4], *al[4], *ar[4], *gamma[4], *beta[4];
    for (int l = 0; l < 4; l++) {
        W[l]     = (const float*)d_in[3 + 5 * l];
        al[l]    = (const float*)d_in[4 + 5 * l];
        ar[l]    = (const float*)d_in[5 + 5 * l];
        gamma[l] = (const float*)d_in[6 + 5 * l];
        beta[l]  = (const float*)d_in[7 + 5 * l];
    }
    const float* W_out = (const float*)d_in[23];
    const float* b_out = (const float*)d_in[24];
    float* out = (float*)d_out;

    cudaFuncSetAttribute(k_gemm, cudaFuncAttributeMaxDynamicSharedMemorySize, GSM_BYTES);

    dim3 ggrid(HD / TN, (MROWS + TM - 1) / TM);

    // launch #4 = k_agg so the profiler's capture slot shows the new agg
    k_csr<<<1, 1024>>>(src, dst);                                // 1
    k_copyx<<<(MROWS * IND + 255) / 256, 256>>>(xx);             // 2
    k_fc0<<<MROWS / FC_ROWS, 256>>>(W[0], al[0], ar[0]);         // 3
    k_agg<<<MROWS / 4, 256>>>();                                 // 4  <-- profiled
    k_wprep<<<dim3(HD, 3), HD>>>(W[1], W[2], W[3]);              // 5
    k_bnfin<<<1, HD>>>(gamma[0], beta[0]);                       // 6
    for (int l = 1; l < 4; l++) {
        k_gemm<<<ggrid, 512, GSM_BYTES>>>(l - 1, al[l], ar[l]);
        k_agg<<<MROWS / 4, 256>>>();
        k_bnfin<<<1, HD>>>(gamma[l], beta[l]);
    }
    k_proj<<<MROWS, 96>>>(W_out, b_out, out, 0);

    for (int step = 1; step < TSTEPS; step++) {
        for (int l = 0; l < 4; l++) {
            if (l == 0)
                k_fc0<<<MROWS / FC_ROWS, 256>>>(W[0], al[0], ar[0]);
            else
                k_gemm<<<ggrid, 512, GSM_BYTES>>>(l - 1, al[l], ar[l]);
            k_agg<<<MROWS / 4, 256>>>();
            k_bnfin<<<1, HD>>>(gamma[l], beta[l]);
        }
        k_proj<<<MROWS, 96>>>(W_out, b_out, out, step);
    }
}

// round 8
// speedup vs baseline: 1.1692x; 1.0239x over previous
#include <cuda_runtime.h>
#include <cuda_bf16.h>
#include <math.h>
#include <stdint.h>

// ---------------- problem constants ----------------
#define BB 8
#define NN 5000
#define EE 80000
#define IND 30
#define HH 4
#define DD 64
#define HD 256
#define OUTD 3
#define TSTEPS 5
#define EPSBN 1e-5f
#define MROWS (BB*NN)   // 40000

// GEMM tiling
#define TM 128
#define TN 128
#define KC 64
#define ASTR 72
#define BSTR 264
#define NPART 64
#define FC_ROWS 16

#define B_BYTES (128 * BSTR * 2)
#define A_BYTES (128 * ASTR * 2)
#define GSM_BYTES (2 * B_BYTES + 4 * A_BYTES)

// ---------------- device scratch ----------------
__device__ float g_x[MROWS * IND];
__device__ float g_h[MROWS * HD];
__device__ float g_hout[MROWS * HD];
__device__ float g_el[MROWS * HH];
__device__ float g_er[MROWS * HH];
__device__ int   g_rowstart[NN + 1];
__device__ int   g_csr_src[EE];
__device__ float g_part[NPART * HD];
__device__ float g_partsq[NPART * HD];
__device__ float g_scale[HD];
__device__ float g_shift[HD];
__device__ __nv_bfloat16 g_wthi[3 * HD * HD];
__device__ __nv_bfloat16 g_wtlo[3 * HD * HD];

__device__ __forceinline__ uint32_t s2u(const void* p) {
    uint32_t a;
    asm("{ .reg .u64 t; cvta.to.shared.u64 t, %1; cvt.u32.u64 %0, t; }" : "=r"(a) : "l"(p));
    return a;
}
__device__ __forceinline__ void ldsm4(uint32_t* r, uint32_t a) {
    asm volatile("ldmatrix.sync.aligned.m8n8.x4.shared.b16 {%0,%1,%2,%3}, [%4];"
                 : "=r"(r[0]), "=r"(r[1]), "=r"(r[2]), "=r"(r[3]) : "r"(a));
}
__device__ __forceinline__ void mma16816(float* c, const uint32_t* a, const uint32_t* b) {
    asm volatile(
        "mma.sync.aligned.m16n8k16.row.col.f32.bf16.bf16.f32 "
        "{%0,%1,%2,%3}, {%4,%5,%6,%7}, {%8,%9}, {%0,%1,%2,%3};"
        : "+f"(c[0]), "+f"(c[1]), "+f"(c[2]), "+f"(c[3])
        : "r"(a[0]), "r"(a[1]), "r"(a[2]), "r"(a[3]), "r"(b[0]), "r"(b[1]));
}

__device__ __forceinline__ float4 lrelu4(float4 a, float s) {
    a.x = a.x > 0.f ? a.x : s * a.x;
    a.y = a.y > 0.f ? a.y : s * a.y;
    a.z = a.z > 0.f ? a.z : s * a.z;
    a.w = a.w > 0.f ? a.w : s * a.w;
    return a;
}

// ---------------- CSR build (single block) ----------------
__global__ __launch_bounds__(1024) void k_csr(const int* __restrict__ src,
                                              const int* __restrict__ dst) {
    __shared__ int s_start[NN];
    __shared__ int s_tmp[1024];
    const int t = threadIdx.x;

    for (int i = t; i < NN; i += 1024) s_start[i] = 0;
    __syncthreads();
    for (int e = t; e < EE; e += 1024) atomicAdd(&s_start[dst[e]], 1);
    __syncthreads();

    int carry = 0;
    for (int base = 0; base < NN; base += 1024) {
        int v = (base + t < NN) ? s_start[base + t] : 0;
        s_tmp[t] = v;
        __syncthreads();
        for (int off = 1; off < 1024; off <<= 1) {
            int x = (t >= off) ? s_tmp[t - off] : 0;
            __syncthreads();
            s_tmp[t] += x;
            __syncthreads();
        }
        int incl = s_tmp[t];
        int tot = s_tmp[1023];
        __syncthreads();
        if (base + t < NN) {
            int ex = carry + incl - v;
            s_start[base + t] = ex;
            g_rowstart[base + t] = ex;
        }
        carry += tot;
    }
    if (t == 0) g_rowstart[NN] = carry;
    __syncthreads();

    for (int e = t; e < EE; e += 1024) {
        int v = dst[e];
        int p = atomicAdd(&s_start[v], 1);
        g_csr_src[p] = src[e];
    }
}

__global__ void k_copyx(const float* __restrict__ xx) {
    int i = blockIdx.x * blockDim.x + threadIdx.x;
    if (i < MROWS * IND) g_x[i] = xx[i];
}

// ---------------- W transpose + bf16 split ----------------
__global__ void k_wprep(const float* __restrict__ W1, const float* __restrict__ W2,
                        const float* __restrict__ W3) {
    int k = blockIdx.x;
    int l = blockIdx.y;
    int n = threadIdx.x;
    const float* W = (l == 0) ? W1 : (l == 1) ? W2 : W3;
    float v = W[k * HD + n];
    __nv_bfloat16 h = __float2bfloat16(v);
    float lo = v - __bfloat162float(h);
    int o = l * HD * HD + n * HD + k;
    g_wthi[o] = h;
    g_wtlo[o] = __float2bfloat16(lo);
}

// ---------------- layer-0 FC ----------------
__global__ __launch_bounds__(256) void k_fc0(const float* __restrict__ W,
                                             const float* __restrict__ al,
                                             const float* __restrict__ ar) {
    __shared__ float sW[IND * HD];
    __shared__ float sx[FC_ROWS * IND];
    __shared__ float pel[FC_ROWS][8], per_[FC_ROWS][8];
    const int t = threadIdx.x;
    const int m0 = blockIdx.x * FC_ROWS;
    const int w = t >> 5, lane = t & 31;

    for (int i = t; i < IND * HD; i += 256) sW[i] = W[i];
    for (int i = t; i < FC_ROWS * IND; i += 256) sx[i] = g_x[m0 * IND + i];
    __syncthreads();

    const float alv = __ldg(&al[t]);
    const float arv = __ldg(&ar[t]);

#pragma unroll
    for (int r = 0; r < FC_ROWS; r++) {
        float acc = 0.f;
#pragma unroll
        for (int k = 0; k < IND; k++) acc = fmaf(sx[r * IND + k], sW[k * HD + t], acc);
        g_h[(size_t)(m0 + r) * HD + t] = acc;
        float ve = acc * alv, vr = acc * arv;
#pragma unroll
        for (int off = 16; off; off >>= 1) {
            ve += __shfl_xor_sync(0xffffffffu, ve, off);
            vr += __shfl_xor_sync(0xffffffffu, vr, off);
        }
        if (lane == 0) { pel[r][w] = ve; per_[r][w] = vr; }
    }
    __syncthreads();
    if (t < FC_ROWS * HH) {
        int r = t >> 2, h = t & 3;
        g_el[(m0 + r) * HH + h] = pel[r][2 * h] + pel[r][2 * h + 1];
        g_er[(m0 + r) * HH + h] = per_[r][2 * h] + per_[r][2 * h + 1];
    }
}

// ---------------- HMMA GEMM: 512 threads, warp tile 32x32 ----------------
__global__ __launch_bounds__(512) void k_gemm(int wsel, const float* __restrict__ al,
                                              const float* __restrict__ ar) {
    extern __shared__ char sm[];
    __shared__ float s_sc[HD], s_sh[HD];
    __shared__ float sh_e[2][128][2][2];
    __nv_bfloat16* Bhi = (__nv_bfloat16*)sm;
    __nv_bfloat16* Blo = Bhi + 128 * BSTR;
    __nv_bfloat16* Abase = Blo + 128 * BSTR;
    const uint32_t uBhi = s2u(Bhi), uBlo = s2u(Blo);
    const uint32_t uA = s2u(Abase);

    const int t = threadIdx.x;
    const int lane = t & 31, warp = t >> 5;
    const int bx = blockIdx.x, by = blockIdx.y;
    const int row0 = by * TM, col0 = bx * TN;
    const int warp_m = (warp >> 2) * 32;
    const int warp_n = (warp & 3) * 32;
    const int head2 = (warp & 3) >> 1;
    const int halfid = warp & 1;
    const int head = bx * 2 + head2;

    if (t < HD) { s_sc[t] = g_scale[t]; s_sh[t] = g_shift[t]; }

    const __nv_bfloat16* wh = g_wthi + wsel * HD * HD;
    const __nv_bfloat16* wl = g_wtlo + wsel * HD * HD;

    {
        int n = t >> 2, kq = (t & 3) * 64;
        int gn = col0 + n;
        const uint4* ph = (const uint4*)&wh[gn * HD + kq];
        const uint4* pl = (const uint4*)&wl[gn * HD + kq];
#pragma unroll
        for (int q = 0; q < 8; q++) {
            *(uint4*)&Bhi[n * BSTR + kq + 8 * q] = __ldg(&ph[q]);
            *(uint4*)&Blo[n * BSTR + kq + 8 * q] = __ldg(&pl[q]);
        }
    }

    float c[2][4][4];
#pragma unroll
    for (int i = 0; i < 2; i++)
#pragma unroll
        for (int j = 0; j < 4; j++)
#pragma unroll
            for (int q = 0; q < 4; q++) c[i][j][q] = 0.f;

    const int a_row = ((lane >> 3) & 1) * 8 + (lane & 7);
    const int a_kof = (lane >> 4) * 8;
    const int b_nsel = (lane >> 4) & 1;
    const int b_ksel = (lane >> 3) & 1;
    const int b_row = (lane & 7);

    auto convA = [&](int ch, int bf) {
        __nv_bfloat16* Ahi = Abase + bf * 2 * 128 * ASTR;
        __nv_bfloat16* Alo = Ahi + 128 * ASTR;
        const int k0 = ch * KC;
        int r = t >> 2, c0i = (t & 3) * 16;
        int grow = row0 + r;
        float x[16];
        if (grow < MROWS) {
            const float4* p = (const float4*)&g_hout[(size_t)grow * HD + k0 + c0i];
#pragma unroll
            for (int q = 0; q < 4; q++) {
                float4 v = p[q];
                x[4 * q + 0] = v.x; x[4 * q + 1] = v.y; x[4 * q + 2] = v.z; x[4 * q + 3] = v.w;
            }
        } else {
#pragma unroll
            for (int j = 0; j < 16; j++) x[j] = 0.f;
        }
#pragma unroll
        for (int j = 0; j < 16; j++) {
            float v = fmaf(x[j], s_sc[k0 + c0i + j], s_sh[k0 + c0i + j]);
            x[j] = v > 0.f ? v : 0.01f * v;
        }
#pragma unroll
        for (int q = 0; q < 2; q++) {
            union { __nv_bfloat16 b[8]; uint4 u; } uh, ul;
#pragma unroll
            for (int j = 0; j < 8; j++) {
                float xv = x[8 * q + j];
                __nv_bfloat16 h = __float2bfloat16(xv);
                uh.b[j] = h;
                ul.b[j] = __float2bfloat16(xv - __bfloat162float(h));
            }
            *(uint4*)&Ahi[r * ASTR + c0i + 8 * q] = uh.u;
            *(uint4*)&Alo[r * ASTR + c0i + 8 * q] = ul.u;
        }
    };

    convA(0, 0);
    __syncthreads();

    for (int ch = 0; ch < 4; ch++) {
        const int bf = ch & 1;
        const uint32_t uAhi = uA + (uint32_t)(bf * 2 * 128 * ASTR * 2);
        const uint32_t uAlo = uAhi + 128 * ASTR * 2;
#pragma unroll
        for (int ks = 0; ks < 4; ks++) {
            const int kg = ch * 4 + ks;
            uint32_t afh[2][4], afl[2][4];
            uint32_t bfh[4][2], bfl[4][2];
#pragma unroll
            for (int mt = 0; mt < 2; mt++) {
                uint32_t off = (uint32_t)(((warp_m + mt * 16 + a_row) * ASTR + 16 * ks + a_kof) * 2);
                ldsm4(afh[mt], uAhi + off);
                ldsm4(afl[mt], uAlo + off);
            }
#pragma unroll
            for (int p = 0; p < 2; p++) {
                uint32_t off = (uint32_t)(((warp_n + (2 * p + b_nsel) * 8 + b_row) * BSTR + 16 * kg + 8 * b_ksel) * 2);
                uint32_t r4[4];
                ldsm4(r4, uBhi + off);
                bfh[2 * p][0] = r4[0]; bfh[2 * p][1] = r4[1];
                bfh[2 * p + 1][0] = r4[2]; bfh[2 * p + 1][1] = r4[3];
                ldsm4(r4, uBlo + off);
                bfl[2 * p][0] = r4[0]; bfl[2 * p][1] = r4[1];
                bfl[2 * p + 1][0] = r4[2]; bfl[2 * p + 1][1] = r4[3];
            }
#pragma unroll
            for (int mt = 0; mt < 2; mt++)
#pragma unroll
                for (int nt = 0; nt < 4; nt++) {
                    mma16816(c[mt][nt], afh[mt], bfh[nt]);
                    mma16816(c[mt][nt], afh[mt], bfl[nt]);
                    mma16816(c[mt][nt], afl[mt], bfh[nt]);
                }
        }
        if (ch < 3) {
            convA(ch + 1, (ch + 1) & 1);
            __syncthreads();
        }
    }

    float elacc[2][2] = {{0.f, 0.f}, {0.f, 0.f}};
    float eracc[2][2] = {{0.f, 0.f}, {0.f, 0.f}};
    const int qn = 2 * (lane & 3);
    const int g = lane >> 2;
#pragma unroll
    for (int mt = 0; mt < 2; mt++) {
#pragma unroll
        for (int nt = 0; nt < 4; nt++) {
            float v0 = c[mt][nt][0], v1 = c[mt][nt][1];
            float v2 = c[mt][nt][2], v3 = c[mt][nt][3];
            int cih = nt * 8 + qn;
            int hcol = halfid * 32 + cih;
            float a0 = __ldg(&al[head * DD + hcol]), a1 = __ldg(&al[head * DD + hcol + 1]);
            float r0 = __ldg(&ar[head * DD + hcol]), r1 = __ldg(&ar[head * DD + hcol + 1]);
            elacc[mt][0] = fmaf(v0, a0, fmaf(v1, a1, elacc[mt][0]));
            elacc[mt][1] = fmaf(v2, a0, fmaf(v3, a1, elacc[mt][1]));
            eracc[mt][0] = fmaf(v0, r0, fmaf(v1, r1, eracc[mt][0]));
            eracc[mt][1] = fmaf(v2, r0, fmaf(v3, r1, eracc[mt][1]));
            int gcol = col0 + warp_n + cih;
            int grow0 = row0 + warp_m + mt * 16 + g;
            int grow1 = grow0 + 8;
            if (grow0 < MROWS) *(float2*)&g_h[(size_t)grow0 * HD + gcol] = make_float2(v0, v1);
            if (grow1 < MROWS) *(float2*)&g_h[(size_t)grow1 * HD + gcol] = make_float2(v2, v3);
        }
    }
#pragma unroll
    for (int mt = 0; mt < 2; mt++)
#pragma unroll
        for (int half = 0; half < 2; half++) {
            float e = elacc[mt][half], r = eracc[mt][half];
            e += __shfl_xor_sync(0xffffffffu, e, 1);
            e += __shfl_xor_sync(0xffffffffu, e, 2);
            r += __shfl_xor_sync(0xffffffffu, r, 1);
            r += __shfl_xor_sync(0xffffffffu, r, 2);
            if ((lane & 3) == 0) {
                int rr = warp_m + mt * 16 + half * 8 + g;
                sh_e[0][rr][head2][halfid] = e;
                sh_e[1][rr][head2][halfid] = r;
            }
        }
    __syncthreads();
    if (t < 256) {
        int rr = t & 127, h2 = t >> 7;
        int row = row0 + rr;
        if (row < MROWS) {
            g_el[row * HH + bx * 2 + h2] = sh_e[0][rr][h2][0] + sh_e[0][rr][h2][1];
            g_er[row * HH + bx * 2 + h2] = sh_e[1][rr][h2][0] + sh_e[1][rr][h2][1];
        }
    }
}

// ---------------- agg: warp per node, 8 nodes/CTA, no block syncs in hot path ----------------
__global__ __launch_bounds__(256) void k_agg() {
    __shared__ float sh_a[8][64][4];      // unnormalized softmax weights
    __shared__ int   sh_src[8][64];
    __shared__ float sh_sum[HD], sh_sq[HD];

    const int t = threadIdx.x;
    const int w = t >> 5, lane = t & 31;
    const int bn = blockIdx.x * 8 + w;
    const int b = bn / NN, v = bn - b * NN;
    const int rowbase = b * NN;
    const int e0 = g_rowstart[v];
    const int deg = g_rowstart[v + 1] - e0;
    const int hc = lane >> 3;             // head of my 8-col group
    const int c0 = lane * 8;

    if (t < HD) { sh_sum[t] = 0.f; sh_sq[t] = 0.f; }
    __syncthreads();

    float4 accA = make_float4(0.f, 0.f, 0.f, 0.f);
    float4 accB = make_float4(0.f, 0.f, 0.f, 0.f);

    if (deg > 0) {
        const float4 erv = *(const float4*)&g_er[bn * HH];

        // ---- softmax: edge-parallel, all 4 heads at once ----
        const bool has0 = lane < deg;
        const bool has1 = lane + 32 < deg;
        int s0c = 0, s1c = 0;
        float4 e0c = make_float4(-INFINITY, -INFINITY, -INFINITY, -INFINITY);
        float4 e1c = e0c;
        if (has0) {
            s0c = g_csr_src[e0 + lane];
            float4 el = *(const float4*)&g_el[(rowbase + s0c) * HH];
            e0c = lrelu4(make_float4(el.x + erv.x, el.y + erv.y, el.z + erv.z, el.w + erv.w), 0.2f);
        }
        if (has1) {
            s1c = g_csr_src[e0 + lane + 32];
            float4 el = *(const float4*)&g_el[(rowbase + s1c) * HH];
            e1c = lrelu4(make_float4(el.x + erv.x, el.y + erv.y, el.z + erv.z, el.w + erv.w), 0.2f);
        }
        float4 m4 = make_float4(fmaxf(e0c.x, e1c.x), fmaxf(e0c.y, e1c.y),
                                fmaxf(e0c.z, e1c.z), fmaxf(e0c.w, e1c.w));
        for (int i = lane + 64; i < deg; i += 32) {    // deg>64 only
            int s = g_csr_src[e0 + i];
            float4 el = *(const float4*)&g_el[(rowbase + s) * HH];
            float4 e = lrelu4(make_float4(el.x + erv.x, el.y + erv.y, el.z + erv.z, el.w + erv.w), 0.2f);
            m4.x = fmaxf(m4.x, e.x); m4.y = fmaxf(m4.y, e.y);
            m4.z = fmaxf(m4.z, e.z); m4.w = fmaxf(m4.w, e.w);
        }
#pragma unroll
        for (int off = 16; off; off >>= 1) {
            m4.x = fmaxf(m4.x, __shfl_xor_sync(0xffffffffu, m4.x, off));
            m4.y = fmaxf(m4.y, __shfl_xor_sync(0xffffffffu, m4.y, off));
            m4.z = fmaxf(m4.z, __shfl_xor_sync(0xffffffffu, m4.z, off));
            m4.w = fmaxf(m4.w, __shfl_xor_sync(0xffffffffu, m4.w, off));
        }
        float4 s4 = make_float4(0.f, 0.f, 0.f, 0.f);
        if (has0) {
            float4 p = make_float4(__expf(e0c.x - m4.x), __expf(e0c.y - m4.y),
                                   __expf(e0c.z - m4.z), __expf(e0c.w - m4.w));
            s4.x += p.x; s4.y += p.y; s4.z += p.z; s4.w += p.w;
            sh_src[w][lane] = s0c;
            *(float4*)&sh_a[w][lane][0] = p;
        }
        if (has1) {
            float4 p = make_float4(__expf(e1c.x - m4.x), __expf(e1c.y - m4.y),
                                   __expf(e1c.z - m4.z), __expf(e1c.w - m4.w));
            s4.x += p.x; s4.y += p.y; s4.z += p.z; s4.w += p.w;
            sh_src[w][lane + 32] = s1c;
            *(float4*)&sh_a[w][lane + 32][0] = p;
        }
        for (int i = lane + 64; i < deg; i += 32) {    // deg>64 only (sum; no store)
            int s = g_csr_src[e0 + i];
            float4 el = *(const float4*)&g_el[(rowbase + s) * HH];
            float4 e = lrelu4(make_float4(el.x + erv.x, el.y + erv.y, el.z + erv.z, el.w + erv.w), 0.2f);
            s4.x += __expf(e.x - m4.x); s4.y += __expf(e.y - m4.y);
            s4.z += __expf(e.z - m4.z); s4.w += __expf(e.w - m4.w);
        }
#pragma unroll
        for (int off = 16; off; off >>= 1) {
            s4.x += __shfl_xor_sync(0xffffffffu, s4.x, off);
            s4.y += __shfl_xor_sync(0xffffffffu, s4.y, off);
            s4.z += __shfl_xor_sync(0xffffffffu, s4.z, off);
            s4.w += __shfl_xor_sync(0xffffffffu, s4.w, off);
        }
        const float inv = 1.f / (hc == 0 ? s4.x : hc == 1 ? s4.y : hc == 2 ? s4.z : s4.w);
        const float mh  = (hc == 0 ? m4.x : hc == 1 ? m4.y : hc == 2 ? m4.z : m4.w);
        const float erh = (hc == 0 ? erv.x : hc == 1 ? erv.y : hc == 2 ? erv.z : erv.w);
        __syncwarp();

        // ---- gather: 32 lanes x 8 cols, 4-edge unroll, 4 independent accs ----
        const float* hb = g_h + (((size_t)rowbase) << 8) + c0;
        float4 acc2 = make_float4(0.f, 0.f, 0.f, 0.f);
        float4 acc3 = make_float4(0.f, 0.f, 0.f, 0.f);
        const int lim = min(deg, 64);
        int i = 0;
        for (; i + 4 <= lim; i += 4) {
            int sa = sh_src[w][i],     sb = sh_src[w][i + 1];
            int sc = sh_src[w][i + 2], sd = sh_src[w][i + 3];
            float wa = sh_a[w][i][hc] * inv,     wb = sh_a[w][i + 1][hc] * inv;
            float wc = sh_a[w][i + 2][hc] * inv, wd = sh_a[w][i + 3][hc] * inv;
            const float4* pa = (const float4*)(hb + ((size_t)sa << 8));
            const float4* pb = (const float4*)(hb + ((size_t)sb << 8));
            const float4* pc = (const float4*)(hb + ((size_t)sc << 8));
            const float4* pd = (const float4*)(hb + ((size_t)sd << 8));
            float4 a0 = pa[0], a1 = pa[1], b0 = pb[0], b1 = pb[1];
            float4 c0v = pc[0], c1 = pc[1], d0 = pd[0], d1 = pd[1];
            accA.x = fmaf(wa, a0.x, accA.x); accA.y = fmaf(wa, a0.y, accA.y);
            accA.z = fmaf(wa, a0.z, accA.z); accA.w = fmaf(wa, a0.w, accA.w);
            accB.x = fmaf(wa, a1.x, accB.x); accB.y = fmaf(wa, a1.y, accB.y);
            accB.z = fmaf(wa, a1.z, accB.z); accB.w = fmaf(wa, a1.w, accB.w);
            acc2.x = fmaf(wb, b0.x, acc2.x); acc2.y = fmaf(wb, b0.y, acc2.y);
            acc2.z = fmaf(wb, b0.z, acc2.z); acc2.w = fmaf(wb, b0.w, acc2.w);
            acc3.x = fmaf(wb, b1.x, acc3.x); acc3.y = fmaf(wb, b1.y, acc3.y);
            acc3.z = fmaf(wb, b1.z, acc3.z); acc3.w = fmaf(wb, b1.w, acc3.w);
            accA.x = fmaf(wc, c0v.x, accA.x); accA.y = fmaf(wc, c0v.y, accA.y);
            accA.z = fmaf(wc, c0v.z, accA.z); accA.w = fmaf(wc, c0v.w, accA.w);
            accB.x = fmaf(wc, c1.x, accB.x); accB.y = fmaf(wc, c1.y, accB.y);
            accB.z = fmaf(wc, c1.z, accB.z); accB.w = fmaf(wc, c1.w, accB.w);
            acc2.x = fmaf(wd, d0.x, acc2.x); acc2.y = fmaf(wd, d0.y, acc2.y);
            acc2.z = fmaf(wd, d0.z, acc2.z); acc2.w = fmaf(wd, d0.w, acc2.w);
            acc3.x = fmaf(wd, d1.x, acc3.x); acc3.y = fmaf(wd, d1.y, acc3.y);
            acc3.z = fmaf(wd, d1.z, acc3.z); acc3.w = fmaf(wd, d1.w, acc3.w);
        }
        for (; i < lim; i++) {
            int s = sh_src[w][i];
            float wv = sh_a[w][i][hc] * inv;
            const float4* p = (const float4*)(hb + ((size_t)s << 8));
            float4 h0 = p[0], h1 = p[1];
            accA.x = fmaf(wv, h0.x, accA.x); accA.y = fmaf(wv, h0.y, accA.y);
            accA.z = fmaf(wv, h0.z, accA.z); accA.w = fmaf(wv, h0.w, accA.w);
            accB.x = fmaf(wv, h1.x, accB.x); accB.y = fmaf(wv, h1.y, accB.y);
            accB.z = fmaf(wv, h1.z, accB.z); accB.w = fmaf(wv, h1.w, accB.w);
        }
        for (i = 64; i < deg; i++) {       // deg>64 tail: recompute alpha inline
            int s = g_csr_src[e0 + i];
            float4 el = *(const float4*)&g_el[(rowbase + s) * HH];
            float e = (hc == 0 ? el.x : hc == 1 ? el.y : hc == 2 ? el.z : el.w) + erh;
            e = e > 0.f ? e : 0.2f * e;
            float wv = __expf(e - mh) * inv;
            const float4* p = (const float4*)(hb + ((size_t)s << 8));
            float4 h0 = p[0], h1 = p[1];
            accA.x = fmaf(wv, h0.x, accA.x); accA.y = fmaf(wv, h0.y, accA.y);
            accA.z = fmaf(wv, h0.z, accA.z); accA.w = fmaf(wv, h0.w, accA.w);
            accB.x = fmaf(wv, h1.x, accB.x); accB.y = fmaf(wv, h1.y, accB.y);
            accB.z = fmaf(wv, h1.z, accB.z); accB.w = fmaf(wv, h1.w, accB.w);
        }
        accA.x += acc2.x; accA.y += acc2.y; accA.z += acc2.z; accA.w += acc2.w;
        accB.x += acc3.x; accB.y += acc3.y; accB.z += acc3.z; accB.w += acc3.w;
    }

    float* outp = g_hout + (size_t)bn * HD + c0;
    *(float4*)outp = accA;
    *(float4*)(outp + 4) = accB;

    // ---- BN partials: smem reduce, then 2 global atomics per thread ----
    atomicAdd(&sh_sum[c0 + 0], accA.x); atomicAdd(&sh_sq[c0 + 0], accA.x * accA.x);
    atomicAdd(&sh_sum[c0 + 1], accA.y); atomicAdd(&sh_sq[c0 + 1], accA.y * accA.y);
    atomicAdd(&sh_sum[c0 + 2], accA.z); atomicAdd(&sh_sq[c0 + 2], accA.z * accA.z);
    atomicAdd(&sh_sum[c0 + 3], accA.w); atomicAdd(&sh_sq[c0 + 3], accA.w * accA.w);
    atomicAdd(&sh_sum[c0 + 4], accB.x); atomicAdd(&sh_sq[c0 + 4], accB.x * accB.x);
    atomicAdd(&sh_sum[c0 + 5], accB.y); atomicAdd(&sh_sq[c0 + 5], accB.y * accB.y);
    atomicAdd(&sh_sum[c0 + 6], accB.z); atomicAdd(&sh_sq[c0 + 6], accB.z * accB.z);
    atomicAdd(&sh_sum[c0 + 7], accB.w); atomicAdd(&sh_sq[c0 + 7], accB.w * accB.w);
    __syncthreads();
    if (t < HD) {
        int slot = (blockIdx.x & (NPART - 1)) * HD + t;
        atomicAdd(&g_part[slot], sh_sum[t]);
        atomicAdd(&g_partsq[slot], sh_sq[t]);
    }
}

// ---------------- BatchNorm finalize ----------------
__global__ void k_bnfin(const float* __restrict__ gamma, const float* __restrict__ beta) {
    int c = threadIdx.x;
    float s = 0.f, sq = 0.f;
#pragma unroll
    for (int i = 0; i < NPART; i++) {
        s  += g_part[i * HD + c];
        sq += g_partsq[i * HD + c];
        g_part[i * HD + c] = 0.f;
        g_partsq[i * HD + c] = 0.f;
    }
    float inv = 1.f / (float)MROWS;
    float mu = s * inv;
    float var = sq * inv - mu * mu;
    float sc = gamma[c] * rsqrtf(var + EPSBN);
    g_scale[c] = sc;
    g_shift[c] = beta[c] - mu * sc;
}

// ---------------- output projection + autoregressive shift ----------------
__global__ void k_proj(const float* __restrict__ Wo, const float* __restrict__ bo,
                       float* __restrict__ out, int step) {
    int bn = blockIdx.x;
    int w = threadIdx.x >> 5, lane = threadIdx.x & 31;
    __shared__ float sval[OUTD];
    const float* hp = g_hout + (size_t)bn * HD;
    float sum = 0.f;
#pragma unroll
    for (int k = lane; k < HD; k += 32) {
        float xv = fmaf(hp[k], g_scale[k], g_shift[k]);
        xv = xv > 0.f ? xv : 0.01f * xv;
        sum = fmaf(xv, Wo[k * OUTD + w], sum);
    }
#pragma unroll
    for (int off = 16; off; off >>= 1) sum += __shfl_xor_sync(0xffffffffu, sum, off);
    if (lane == 0) sval[w] = sum + bo[w];

    float keep = 0.f;
    if (threadIdx.x < IND - OUTD) keep = g_x[bn * IND + threadIdx.x + OUTD];
    __syncthreads();
    if (threadIdx.x < IND - OUTD) g_x[bn * IND + threadIdx.x] = keep;
    else if (threadIdx.x < IND) g_x[bn * IND + threadIdx.x] = sval[threadIdx.x - (IND - OUTD)];
    if (threadIdx.x < OUTD) out[(bn * TSTEPS + step) * OUTD + threadIdx.x] = sval[threadIdx.x];
}

// ---------------- launcher ----------------
extern "C" void kernel_launch(void* const* d_in, const int* in_sizes, int n_in,
                              void* d_out, int out_size) {
    const float* xx  = (const float*)d_in[0];
    const int*   src = (const int*)d_in[1];
    const int*   dst = (const int*)d_in[2];
    const float *W[4], *al[4], *ar[4], *gamma[4], *beta[4];
    for (int l = 0; l < 4; l++) {
        W[l]     = (const float*)d_in[3 + 5 * l];
        al[l]    = (const float*)d_in[4 + 5 * l];
        ar[l]    = (const float*)d_in[5 + 5 * l];
        gamma[l] = (const float*)d_in[6 + 5 * l];
        beta[l]  = (const float*)d_in[7 + 5 * l];
    }
    const float* W_out = (const float*)d_in[23];
    const float* b_out = (const float*)d_in[24];
    float* out = (float*)d_out;

    cudaFuncSetAttribute(k_gemm, cudaFuncAttributeMaxDynamicSharedMemorySize, GSM_BYTES);

    dim3 ggrid(HD / TN, (MROWS + TM - 1) / TM);

    // launch #4 = k_agg (the kernel changed this round) for the profiler slot
    k_csr<<<1, 1024>>>(src, dst);                                // 1
    k_copyx<<<(MROWS * IND + 255) / 256, 256>>>(xx);             // 2
    k_fc0<<<MROWS / FC_ROWS, 256>>>(W[0], al[0], ar[0]);         // 3
    k_agg<<<MROWS / 8, 256>>>();                                 // 4  <-- profiled
    k_wprep<<<dim3(HD, 3), HD>>>(W[1], W[2], W[3]);              // 5
    k_bnfin<<<1, HD>>>(gamma[0], beta[0]);                       // 6
    for (int l = 1; l < 4; l++) {
        k_gemm<<<ggrid, 512, GSM_BYTES>>>(l - 1, al[l], ar[l]);
        k_agg<<<MROWS / 8, 256>>>();
        k_bnfin<<<1, HD>>>(gamma[l], beta[l]);
    }
    k_proj<<<MROWS, 96>>>(W_out, b_out, out, 0);

    for (int step = 1; step < TSTEPS; step++) {
        for (int l = 0; l < 4; l++) {
            if (l == 0)
                k_fc0<<<MROWS / FC_ROWS, 256>>>(W[0], al[0], ar[0]);
            else
                k_gemm<<<ggrid, 512, GSM_BYTES>>>(l - 1, al[l], ar[l]);
            k_agg<<<MROWS / 8, 256>>>();
            k_bnfin<<<1, HD>>>(gamma[l], beta[l]);
        }
        k_proj<<<MROWS, 96>>>(W_out, b_out, out, step);
    }
}

// round 10
// speedup vs baseline: 1.4200x; 1.2145x over previous
#include <cuda_runtime.h>
#include <cuda_bf16.h>
#include <math.h>
#include <stdint.h>

// ---------------- problem constants ----------------
#define BB 8
#define NN 5000
#define EE 80000
#define IND 30
#define HH 4
#define DD 64
#define HD 256
#define OUTD 3
#define TSTEPS 5
#define EPSBN 1e-5f
#define MROWS (BB*NN)   // 40000

// GEMM tiling
#define TM 128
#define TN 128
#define KC 64
#define ASTR 72
#define BSTR 264
#define NPART 64
#define FC_ROWS 16

#define B_BYTES (128 * BSTR * 2)
#define A_BYTES (128 * ASTR * 2)
#define GSM_BYTES (2 * B_BYTES + 4 * A_BYTES)

// ---------------- device scratch ----------------
__device__ float g_x[MROWS * IND];
__device__ float g_h[MROWS * HD];
__device__ float g_hout[MROWS * HD];
__device__ float g_el[MROWS * HH];
__device__ float g_er[MROWS * HH];
__device__ int   g_rowstart[NN + 1];
__device__ int   g_csr_src[EE];
__device__ float g_part[NPART * HD];
__device__ float g_partsq[NPART * HD];
__device__ float g_scale[HD];
__device__ float g_shift[HD];
__device__ __nv_bfloat16 g_wthi[3 * HD * HD];
__device__ __nv_bfloat16 g_wtlo[3 * HD * HD];

__device__ __forceinline__ uint32_t s2u(const void* p) {
    uint32_t a;
    asm("{ .reg .u64 t; cvta.to.shared.u64 t, %1; cvt.u32.u64 %0, t; }" : "=r"(a) : "l"(p));
    return a;
}
__device__ __forceinline__ void ldsm4(uint32_t* r, uint32_t a) {
    asm volatile("ldmatrix.sync.aligned.m8n8.x4.shared.b16 {%0,%1,%2,%3}, [%4];"
                 : "=r"(r[0]), "=r"(r[1]), "=r"(r[2]), "=r"(r[3]) : "r"(a));
}
__device__ __forceinline__ void mma16816(float* c, const uint32_t* a, const uint32_t* b) {
    asm volatile(
        "mma.sync.aligned.m16n8k16.row.col.f32.bf16.bf16.f32 "
        "{%0,%1,%2,%3}, {%4,%5,%6,%7}, {%8,%9}, {%0,%1,%2,%3};"
        : "+f"(c[0]), "+f"(c[1]), "+f"(c[2]), "+f"(c[3])
        : "r"(a[0]), "r"(a[1]), "r"(a[2]), "r"(a[3]), "r"(b[0]), "r"(b[1]));
}
__device__ __forceinline__ float4 lrelu4(float4 a, float s) {
    a.x = a.x > 0.f ? a.x : s * a.x;
    a.y = a.y > 0.f ? a.y : s * a.y;
    a.z = a.z > 0.f ? a.z : s * a.z;
    a.w = a.w > 0.f ? a.w : s * a.w;
    return a;
}

// ---------------- CSR build (single block) ----------------
__global__ __launch_bounds__(1024) void k_csr(const int* __restrict__ src,
                                              const int* __restrict__ dst) {
    __shared__ int s_start[NN];
    __shared__ int s_tmp[1024];
    const int t = threadIdx.x;

    for (int i = t; i < NN; i += 1024) s_start[i] = 0;
    __syncthreads();
    for (int e = t; e < EE; e += 1024) atomicAdd(&s_start[dst[e]], 1);
    __syncthreads();

    int carry = 0;
    for (int base = 0; base < NN; base += 1024) {
        int v = (base + t < NN) ? s_start[base + t] : 0;
        s_tmp[t] = v;
        __syncthreads();
        for (int off = 1; off < 1024; off <<= 1) {
            int x = (t >= off) ? s_tmp[t - off] : 0;
            __syncthreads();
            s_tmp[t] += x;
            __syncthreads();
        }
        int incl = s_tmp[t];
        int tot = s_tmp[1023];
        __syncthreads();
        if (base + t < NN) {
            int ex = carry + incl - v;
            s_start[base + t] = ex;
            g_rowstart[base + t] = ex;
        }
        carry += tot;
    }
    if (t == 0) g_rowstart[NN] = carry;
    __syncthreads();

    for (int e = t; e < EE; e += 1024) {
        int v = dst[e];
        int p = atomicAdd(&s_start[v], 1);
        g_csr_src[p] = src[e];
    }
}

__global__ void k_copyx(const float* __restrict__ xx) {
    int i = blockIdx.x * blockDim.x + threadIdx.x;
    if (i < MROWS * IND) g_x[i] = xx[i];
}

// ---------------- W transpose + bf16 split ----------------
__global__ void k_wprep(const float* __restrict__ W1, const float* __restrict__ W2,
                        const float* __restrict__ W3) {
    int k = blockIdx.x;
    int l = blockIdx.y;
    int n = threadIdx.x;
    const float* W = (l == 0) ? W1 : (l == 1) ? W2 : W3;
    float v = W[k * HD + n];
    __nv_bfloat16 h = __float2bfloat16(v);
    float lo = v - __bfloat162float(h);
    int o = l * HD * HD + n * HD + k;
    g_wthi[o] = h;
    g_wtlo[o] = __float2bfloat16(lo);
}

// ---------------- layer-0 FC ----------------
__global__ __launch_bounds__(256) void k_fc0(const float* __restrict__ W,
                                             const float* __restrict__ al,
                                             const float* __restrict__ ar) {
    __shared__ float sW[IND * HD];
    __shared__ float sx[FC_ROWS * IND];
    __shared__ float pel[FC_ROWS][8], per_[FC_ROWS][8];
    const int t = threadIdx.x;
    const int m0 = blockIdx.x * FC_ROWS;
    const int w = t >> 5, lane = t & 31;

    for (int i = t; i < IND * HD; i += 256) sW[i] = W[i];
    for (int i = t; i < FC_ROWS * IND; i += 256) sx[i] = g_x[m0 * IND + i];
    __syncthreads();

    const float alv = __ldg(&al[t]);
    const float arv = __ldg(&ar[t]);

#pragma unroll
    for (int r = 0; r < FC_ROWS; r++) {
        float acc = 0.f;
#pragma unroll
        for (int k = 0; k < IND; k++) acc = fmaf(sx[r * IND + k], sW[k * HD + t], acc);
        g_h[(size_t)(m0 + r) * HD + t] = acc;
        float ve = acc * alv, vr = acc * arv;
#pragma unroll
        for (int off = 16; off; off >>= 1) {
            ve += __shfl_xor_sync(0xffffffffu, ve, off);
            vr += __shfl_xor_sync(0xffffffffu, vr, off);
        }
        if (lane == 0) { pel[r][w] = ve; per_[r][w] = vr; }
    }
    __syncthreads();
    if (t < FC_ROWS * HH) {
        int r = t >> 2, h = t & 3;
        g_el[(m0 + r) * HH + h] = pel[r][2 * h] + pel[r][2 * h + 1];
        g_er[(m0 + r) * HH + h] = per_[r][2 * h] + per_[r][2 * h + 1];
    }
}

// ---------------- HMMA GEMM: 512 threads, warp tile 32x32 ----------------
__global__ __launch_bounds__(512) void k_gemm(int wsel, const float* __restrict__ al,
                                              const float* __restrict__ ar) {
    extern __shared__ char sm[];
    __shared__ float s_sc[HD], s_sh[HD];
    __shared__ float sh_e[2][128][2][2];
    __nv_bfloat16* Bhi = (__nv_bfloat16*)sm;
    __nv_bfloat16* Blo = Bhi + 128 * BSTR;
    __nv_bfloat16* Abase = Blo + 128 * BSTR;
    const uint32_t uBhi = s2u(Bhi), uBlo = s2u(Blo);
    const uint32_t uA = s2u(Abase);

    const int t = threadIdx.x;
    const int lane = t & 31, warp = t >> 5;
    const int bx = blockIdx.x, by = blockIdx.y;
    const int row0 = by * TM, col0 = bx * TN;
    const int warp_m = (warp >> 2) * 32;
    const int warp_n = (warp & 3) * 32;
    const int head2 = (warp & 3) >> 1;
    const int halfid = warp & 1;
    const int head = bx * 2 + head2;

    if (t < HD) { s_sc[t] = g_scale[t]; s_sh[t] = g_shift[t]; }

    const __nv_bfloat16* wh = g_wthi + wsel * HD * HD;
    const __nv_bfloat16* wl = g_wtlo + wsel * HD * HD;

    {
        int n = t >> 2, kq = (t & 3) * 64;
        int gn = col0 + n;
        const uint4* ph = (const uint4*)&wh[gn * HD + kq];
        const uint4* pl = (const uint4*)&wl[gn * HD + kq];
#pragma unroll
        for (int q = 0; q < 8; q++) {
            *(uint4*)&Bhi[n * BSTR + kq + 8 * q] = __ldg(&ph[q]);
            *(uint4*)&Blo[n * BSTR + kq + 8 * q] = __ldg(&pl[q]);
        }
    }

    float c[2][4][4];
#pragma unroll
    for (int i = 0; i < 2; i++)
#pragma unroll
        for (int j = 0; j < 4; j++)
#pragma unroll
            for (int q = 0; q < 4; q++) c[i][j][q] = 0.f;

    const int a_row = ((lane >> 3) & 1) * 8 + (lane & 7);
    const int a_kof = (lane >> 4) * 8;
    const int b_nsel = (lane >> 4) & 1;
    const int b_ksel = (lane >> 3) & 1;
    const int b_row = (lane & 7);

    auto convA = [&](int ch, int bf) {
        __nv_bfloat16* Ahi = Abase + bf * 2 * 128 * ASTR;
        __nv_bfloat16* Alo = Ahi + 128 * ASTR;
        const int k0 = ch * KC;
        int r = t >> 2, c0i = (t & 3) * 16;
        int grow = row0 + r;
        float x[16];
        if (grow < MROWS) {
            const float4* p = (const float4*)&g_hout[(size_t)grow * HD + k0 + c0i];
#pragma unroll
            for (int q = 0; q < 4; q++) {
                float4 v = p[q];
                x[4 * q + 0] = v.x; x[4 * q + 1] = v.y; x[4 * q + 2] = v.z; x[4 * q + 3] = v.w;
            }
        } else {
#pragma unroll
            for (int j = 0; j < 16; j++) x[j] = 0.f;
        }
#pragma unroll
        for (int j = 0; j < 16; j++) {
            float v = fmaf(x[j], s_sc[k0 + c0i + j], s_sh[k0 + c0i + j]);
            x[j] = v > 0.f ? v : 0.01f * v;
        }
#pragma unroll
        for (int q = 0; q < 2; q++) {
            union { __nv_bfloat16 b[8]; uint4 u; } uh, ul;
#pragma unroll
            for (int j = 0; j < 8; j++) {
                float xv = x[8 * q + j];
                __nv_bfloat16 h = __float2bfloat16(xv);
                uh.b[j] = h;
                ul.b[j] = __float2bfloat16(xv - __bfloat162float(h));
            }
            *(uint4*)&Ahi[r * ASTR + c0i + 8 * q] = uh.u;
            *(uint4*)&Alo[r * ASTR + c0i + 8 * q] = ul.u;
        }
    };

    convA(0, 0);
    __syncthreads();

    for (int ch = 0; ch < 4; ch++) {
        const int bf = ch & 1;
        const uint32_t uAhi = uA + (uint32_t)(bf * 2 * 128 * ASTR * 2);
        const uint32_t uAlo = uAhi + 128 * ASTR * 2;
#pragma unroll
        for (int ks = 0; ks < 4; ks++) {
            const int kg = ch * 4 + ks;
            uint32_t afh[2][4], afl[2][4];
            uint32_t bfh[4][2], bfl[4][2];
#pragma unroll
            for (int mt = 0; mt < 2; mt++) {
                uint32_t off = (uint32_t)(((warp_m + mt * 16 + a_row) * ASTR + 16 * ks + a_kof) * 2);
                ldsm4(afh[mt], uAhi + off);
                ldsm4(afl[mt], uAlo + off);
            }
#pragma unroll
            for (int p = 0; p < 2; p++) {
                uint32_t off = (uint32_t)(((warp_n + (2 * p + b_nsel) * 8 + b_row) * BSTR + 16 * kg + 8 * b_ksel) * 2);
                uint32_t r4[4];
                ldsm4(r4, uBhi + off);
                bfh[2 * p][0] = r4[0]; bfh[2 * p][1] = r4[1];
                bfh[2 * p + 1][0] = r4[2]; bfh[2 * p + 1][1] = r4[3];
                ldsm4(r4, uBlo + off);
                bfl[2 * p][0] = r4[0]; bfl[2 * p][1] = r4[1];
                bfl[2 * p + 1][0] = r4[2]; bfl[2 * p + 1][1] = r4[3];
            }
#pragma unroll
            for (int mt = 0; mt < 2; mt++)
#pragma unroll
                for (int nt = 0; nt < 4; nt++) {
                    mma16816(c[mt][nt], afh[mt], bfh[nt]);
                    mma16816(c[mt][nt], afh[mt], bfl[nt]);
                    mma16816(c[mt][nt], afl[mt], bfh[nt]);
                }
        }
        if (ch < 3) {
            convA(ch + 1, (ch + 1) & 1);
            __syncthreads();
        }
    }

    float elacc[2][2] = {{0.f, 0.f}, {0.f, 0.f}};
    float eracc[2][2] = {{0.f, 0.f}, {0.f, 0.f}};
    const int qn = 2 * (lane & 3);
    const int g = lane >> 2;
#pragma unroll
    for (int mt = 0; mt < 2; mt++) {
#pragma unroll
        for (int nt = 0; nt < 4; nt++) {
            float v0 = c[mt][nt][0], v1 = c[mt][nt][1];
            float v2 = c[mt][nt][2], v3 = c[mt][nt][3];
            int cih = nt * 8 + qn;
            int hcol = halfid * 32 + cih;
            float a0 = __ldg(&al[head * DD + hcol]), a1 = __ldg(&al[head * DD + hcol + 1]);
            float r0 = __ldg(&ar[head * DD + hcol]), r1 = __ldg(&ar[head * DD + hcol + 1]);
            elacc[mt][0] = fmaf(v0, a0, fmaf(v1, a1, elacc[mt][0]));
            elacc[mt][1] = fmaf(v2, a0, fmaf(v3, a1, elacc[mt][1]));
            eracc[mt][0] = fmaf(v0, r0, fmaf(v1, r1, eracc[mt][0]));
            eracc[mt][1] = fmaf(v2, r0, fmaf(v3, r1, eracc[mt][1]));
            int gcol = col0 + warp_n + cih;
            int grow0 = row0 + warp_m + mt * 16 + g;
            int grow1 = grow0 + 8;
            if (grow0 < MROWS) *(float2*)&g_h[(size_t)grow0 * HD + gcol] = make_float2(v0, v1);
            if (grow1 < MROWS) *(float2*)&g_h[(size_t)grow1 * HD + gcol] = make_float2(v2, v3);
        }
    }
#pragma unroll
    for (int mt = 0; mt < 2; mt++)
#pragma unroll
        for (int half = 0; half < 2; half++) {
            float e = elacc[mt][half], r = eracc[mt][half];
            e += __shfl_xor_sync(0xffffffffu, e, 1);
            e += __shfl_xor_sync(0xffffffffu, e, 2);
            r += __shfl_xor_sync(0xffffffffu, r, 1);
            r += __shfl_xor_sync(0xffffffffu, r, 2);
            if ((lane & 3) == 0) {
                int rr = warp_m + mt * 16 + half * 8 + g;
                sh_e[0][rr][head2][halfid] = e;
                sh_e[1][rr][head2][halfid] = r;
            }
        }
    __syncthreads();
    if (t < 256) {
        int rr = t & 127, h2 = t >> 7;
        int row = row0 + rr;
        if (row < MROWS) {
            g_el[row * HH + bx * 2 + h2] = sh_e[0][rr][h2][0] + sh_e[0][rr][h2][1];
            g_er[row * HH + bx * 2 + h2] = sh_e[1][rr][h2][0] + sh_e[1][rr][h2][1];
        }
    }
}

// ---------------- agg: warp/node, 8 nodes/CTA, no shared atomics ----------------
__global__ __launch_bounds__(256) void k_agg() {
    __shared__ float sh_a[8][32][4];     // unnormalized softmax weights (first 32 edges)
    __shared__ int   sh_src[8][32];
    __shared__ float sh_ws[8][HD];       // per-warp BN sum staging
    __shared__ float sh_wq[8][HD];       // per-warp BN sumsq staging

    const int t = threadIdx.x;
    const int w = t >> 5, lane = t & 31;
    const int bn = blockIdx.x * 8 + w;
    const int b = bn / NN, v = bn - b * NN;
    const int rowbase = b * NN;
    const int e0 = g_rowstart[v];
    const int deg = g_rowstart[v + 1] - e0;
    const int hc = lane >> 3;            // head of my 8-col group
    const int c0 = lane * 8;

    float4 accA = make_float4(0.f, 0.f, 0.f, 0.f);
    float4 accB = make_float4(0.f, 0.f, 0.f, 0.f);

    if (deg > 0) {
        const float4 erv = *(const float4*)&g_er[bn * HH];

        // ---- softmax over edges (all 4 heads), first 32 cached ----
        const bool has0 = lane < deg;
        int s0c = 0;
        float4 e0c = make_float4(-INFINITY, -INFINITY, -INFINITY, -INFINITY);
        if (has0) {
            s0c = g_csr_src[e0 + lane];
            float4 el = *(const float4*)&g_el[(rowbase + s0c) * HH];
            e0c = lrelu4(make_float4(el.x + erv.x, el.y + erv.y, el.z + erv.z, el.w + erv.w), 0.2f);
        }
        float4 m4 = e0c;
        for (int i = lane + 32; i < deg; i += 32) {
            int s = g_csr_src[e0 + i];
            float4 el = *(const float4*)&g_el[(rowbase + s) * HH];
            float4 e = lrelu4(make_float4(el.x + erv.x, el.y + erv.y, el.z + erv.z, el.w + erv.w), 0.2f);
            m4.x = fmaxf(m4.x, e.x); m4.y = fmaxf(m4.y, e.y);
            m4.z = fmaxf(m4.z, e.z); m4.w = fmaxf(m4.w, e.w);
        }
#pragma unroll
        for (int off = 16; off; off >>= 1) {
            m4.x = fmaxf(m4.x, __shfl_xor_sync(0xffffffffu, m4.x, off));
            m4.y = fmaxf(m4.y, __shfl_xor_sync(0xffffffffu, m4.y, off));
            m4.z = fmaxf(m4.z, __shfl_xor_sync(0xffffffffu, m4.z, off));
            m4.w = fmaxf(m4.w, __shfl_xor_sync(0xffffffffu, m4.w, off));
        }
        float4 s4 = make_float4(0.f, 0.f, 0.f, 0.f);
        if (has0) {
            float4 p = make_float4(__expf(e0c.x - m4.x), __expf(e0c.y - m4.y),
                                   __expf(e0c.z - m4.z), __expf(e0c.w - m4.w));
            s4 = p;
            sh_src[w][lane] = s0c;
            *(float4*)&sh_a[w][lane][0] = p;
        }
        for (int i = lane + 32; i < deg; i += 32) {
            int s = g_csr_src[e0 + i];
            float4 el = *(const float4*)&g_el[(rowbase + s) * HH];
            float4 e = lrelu4(make_float4(el.x + erv.x, el.y + erv.y, el.z + erv.z, el.w + erv.w), 0.2f);
            s4.x += __expf(e.x - m4.x); s4.y += __expf(e.y - m4.y);
            s4.z += __expf(e.z - m4.z); s4.w += __expf(e.w - m4.w);
        }
#pragma unroll
        for (int off = 16; off; off >>= 1) {
            s4.x += __shfl_xor_sync(0xffffffffu, s4.x, off);
            s4.y += __shfl_xor_sync(0xffffffffu, s4.y, off);
            s4.z += __shfl_xor_sync(0xffffffffu, s4.z, off);
            s4.w += __shfl_xor_sync(0xffffffffu, s4.w, off);
        }
        const float inv = 1.f / (hc == 0 ? s4.x : hc == 1 ? s4.y : hc == 2 ? s4.z : s4.w);
        const float mh  = (hc == 0 ? m4.x : hc == 1 ? m4.y : hc == 2 ? m4.z : m4.w);
        const float erh = (hc == 0 ? erv.x : hc == 1 ? erv.y : hc == 2 ? erv.z : erv.w);
        __syncwarp();

        // ---- gather: 32 lanes x 8 cols, 4-edge unroll ----
        const float* hb = g_h + (((size_t)rowbase) << 8) + c0;
        float4 acc2 = make_float4(0.f, 0.f, 0.f, 0.f);
        float4 acc3 = make_float4(0.f, 0.f, 0.f, 0.f);
        const int lim = min(deg, 32);
        int i = 0;
        for (; i + 4 <= lim; i += 4) {
            int sa = sh_src[w][i],     sb = sh_src[w][i + 1];
            int sc = sh_src[w][i + 2], sd = sh_src[w][i + 3];
            float wa = sh_a[w][i][hc] * inv,     wb = sh_a[w][i + 1][hc] * inv;
            float wc = sh_a[w][i + 2][hc] * inv, wd = sh_a[w][i + 3][hc] * inv;
            const float4* pa = (const float4*)(hb + ((size_t)sa << 8));
            const float4* pb = (const float4*)(hb + ((size_t)sb << 8));
            const float4* pc = (const float4*)(hb + ((size_t)sc << 8));
            const float4* pd = (const float4*)(hb + ((size_t)sd << 8));
            float4 a0 = pa[0], a1 = pa[1], b0 = pb[0], b1 = pb[1];
            float4 c0v = pc[0], c1 = pc[1], d0 = pd[0], d1 = pd[1];
            accA.x = fmaf(wa, a0.x, accA.x); accA.y = fmaf(wa, a0.y, accA.y);
            accA.z = fmaf(wa, a0.z, accA.z); accA.w = fmaf(wa, a0.w, accA.w);
            accB.x = fmaf(wa, a1.x, accB.x); accB.y = fmaf(wa, a1.y, accB.y);
            accB.z = fmaf(wa, a1.z, accB.z); accB.w = fmaf(wa, a1.w, accB.w);
            acc2.x = fmaf(wb, b0.x, acc2.x); acc2.y = fmaf(wb, b0.y, acc2.y);
            acc2.z = fmaf(wb, b0.z, acc2.z); acc2.w = fmaf(wb, b0.w, acc2.w);
            acc3.x = fmaf(wb, b1.x, acc3.x); acc3.y = fmaf(wb, b1.y, acc3.y);
            acc3.z = fmaf(wb, b1.z, acc3.z); acc3.w = fmaf(wb, b1.w, acc3.w);
            accA.x = fmaf(wc, c0v.x, accA.x); accA.y = fmaf(wc, c0v.y, accA.y);
            accA.z = fmaf(wc, c0v.z, accA.z); accA.w = fmaf(wc, c0v.w, accA.w);
            accB.x = fmaf(wc, c1.x, accB.x); accB.y = fmaf(wc, c1.y, accB.y);
            accB.z = fmaf(wc, c1.z, accB.z); accB.w = fmaf(wc, c1.w, accB.w);
            acc2.x = fmaf(wd, d0.x, acc2.x); acc2.y = fmaf(wd, d0.y, acc2.y);
            acc2.z = fmaf(wd, d0.z, acc2.z); acc2.w = fmaf(wd, d0.w, acc2.w);
            acc3.x = fmaf(wd, d1.x, acc3.x); acc3.y = fmaf(wd, d1.y, acc3.y);
            acc3.z = fmaf(wd, d1.z, acc3.z); acc3.w = fmaf(wd, d1.w, acc3.w);
        }
        for (; i < lim; i++) {
            int s = sh_src[w][i];
            float wv = sh_a[w][i][hc] * inv;
            const float4* p = (const float4*)(hb + ((size_t)s << 8));
            float4 h0 = p[0], h1 = p[1];
            accA.x = fmaf(wv, h0.x, accA.x); accA.y = fmaf(wv, h0.y, accA.y);
            accA.z = fmaf(wv, h0.z, accA.z); accA.w = fmaf(wv, h0.w, accA.w);
            accB.x = fmaf(wv, h1.x, accB.x); accB.y = fmaf(wv, h1.y, accB.y);
            accB.z = fmaf(wv, h1.z, accB.z); accB.w = fmaf(wv, h1.w, accB.w);
        }
        for (i = 32; i < deg; i++) {        // rare tail: recompute alpha inline
            int s = g_csr_src[e0 + i];
            float4 el = *(const float4*)&g_el[(rowbase + s) * HH];
            float e = (hc == 0 ? el.x : hc == 1 ? el.y : hc == 2 ? el.z : el.w) + erh;
            e = e > 0.f ? e : 0.2f * e;
            float wv = __expf(e - mh) * inv;
            const float4* p = (const float4*)(hb + ((size_t)s << 8));
            float4 h0 = p[0], h1 = p[1];
            accA.x = fmaf(wv, h0.x, accA.x); accA.y = fmaf(wv, h0.y, accA.y);
            accA.z = fmaf(wv, h0.z, accA.z); accA.w = fmaf(wv, h0.w, accA.w);
            accB.x = fmaf(wv, h1.x, accB.x); accB.y = fmaf(wv, h1.y, accB.y);
            accB.z = fmaf(wv, h1.z, accB.z); accB.w = fmaf(wv, h1.w, accB.w);
        }
        accA.x += acc2.x; accA.y += acc2.y; accA.z += acc2.z; accA.w += acc2.w;
        accB.x += acc3.x; accB.y += acc3.y; accB.z += acc3.z; accB.w += acc3.w;
    }

    float* outp = g_hout + (size_t)bn * HD + c0;
    *(float4*)outp = accA;
    *(float4*)(outp + 4) = accB;

    // ---- BN partials: per-warp staging, block reduce, 1 REDG pair ----
    *(float4*)&sh_ws[w][c0]     = accA;
    *(float4*)&sh_ws[w][c0 + 4] = accB;
    *(float4*)&sh_wq[w][c0]     = make_float4(accA.x * accA.x, accA.y * accA.y,
                                              accA.z * accA.z, accA.w * accA.w);
    *(float4*)&sh_wq[w][c0 + 4] = make_float4(accB.x * accB.x, accB.y * accB.y,
                                              accB.z * accB.z, accB.w * accB.w);
    __syncthreads();
    if (t < HD) {
        float s = 0.f, sq = 0.f;
#pragma unroll
        for (int wi = 0; wi < 8; wi++) { s += sh_ws[wi][t]; sq += sh_wq[wi][t]; }
        int slot = (blockIdx.x & (NPART - 1)) * HD + t;
        atomicAdd(&g_part[slot], s);
        atomicAdd(&g_partsq[slot], sq);
    }
}

// ---------------- BatchNorm finalize ----------------
__global__ void k_bnfin(const float* __restrict__ gamma, const float* __restrict__ beta) {
    int c = threadIdx.x;
    float s = 0.f, sq = 0.f;
#pragma unroll
    for (int i = 0; i < NPART; i++) {
        s  += g_part[i * HD + c];
        sq += g_partsq[i * HD + c];
        g_part[i * HD + c] = 0.f;
        g_partsq[i * HD + c] = 0.f;
    }
    float inv = 1.f / (float)MROWS;
    float mu = s * inv;
    float var = sq * inv - mu * mu;
    float sc = gamma[c] * rsqrtf(var + EPSBN);
    g_scale[c] = sc;
    g_shift[c] = beta[c] - mu * sc;
}

// ---------------- output projection: warp per node, 8 nodes/CTA ----------------
__global__ __launch_bounds__(256) void k_proj(const float* __restrict__ Wo,
                                              const float* __restrict__ bo,
                                              float* __restrict__ out, int step) {
    __shared__ float sWo[HD * OUTD];
    const int t = threadIdx.x;
    const int w = t >> 5, lane = t & 31;
    const int bn = blockIdx.x * 8 + w;

    for (int i = t; i < HD * OUTD; i += 256) sWo[i] = Wo[i];   // FIX: strided fill
    __syncthreads();

    const float* hp = g_hout + (size_t)bn * HD;
    float s0 = 0.f, s1 = 0.f, s2 = 0.f;
#pragma unroll
    for (int q = 0; q < 8; q++) {
        int k = lane * 8 + q;
        float xv = fmaf(hp[k], g_scale[k], g_shift[k]);
        xv = xv > 0.f ? xv : 0.01f * xv;
        s0 = fmaf(xv, sWo[k * OUTD + 0], s0);
        s1 = fmaf(xv, sWo[k * OUTD + 1], s1);
        s2 = fmaf(xv, sWo[k * OUTD + 2], s2);
    }
#pragma unroll
    for (int off = 16; off; off >>= 1) {
        s0 += __shfl_xor_sync(0xffffffffu, s0, off);
        s1 += __shfl_xor_sync(0xffffffffu, s1, off);
        s2 += __shfl_xor_sync(0xffffffffu, s2, off);
    }
    s0 += __ldg(&bo[0]); s1 += __ldg(&bo[1]); s2 += __ldg(&bo[2]);

    float keep = 0.f;
    if (lane < IND - OUTD) keep = g_x[bn * IND + lane + OUTD];
    __syncwarp();
    if (lane < IND - OUTD) g_x[bn * IND + lane] = keep;
    else if (lane < IND) g_x[bn * IND + lane] = (lane == 27 ? s0 : lane == 28 ? s1 : s2);
    if (lane < OUTD) out[(bn * TSTEPS + step) * OUTD + lane] = (lane == 0 ? s0 : lane == 1 ? s1 : s2);
}

// ---------------- launcher ----------------
extern "C" void kernel_launch(void* const* d_in, const int* in_sizes, int n_in,
                              void* d_out, int out_size) {
    const float* xx  = (const float*)d_in[0];
    const int*   src = (const int*)d_in[1];
    const int*   dst = (const int*)d_in[2];
    const float *W[4], *al[4], *ar[4], *gamma[4], *beta[4];
    for (int l = 0; l < 4; l++) {
        W[l]     = (const float*)d_in[3 + 5 * l];
        al[l]    = (const float*)d_in[4 + 5 * l];
        ar[l]    = (const float*)d_in[5 + 5 * l];
        gamma[l] = (const float*)d_in[6 + 5 * l];
        beta[l]  = (const float*)d_in[7 + 5 * l];
    }
    const float* W_out = (const float*)d_in[23];
    const float* b_out = (const float*)d_in[24];
    float* out = (float*)d_out;

    cudaFuncSetAttribute(k_gemm, cudaFuncAttributeMaxDynamicSharedMemorySize, GSM_BYTES);

    dim3 ggrid(HD / TN, (MROWS + TM - 1) / TM);

    // launch #4 = k_agg for the profiler slot
    k_csr<<<1, 1024>>>(src, dst);                                // 1
    k_copyx<<<(MROWS * IND + 255) / 256, 256>>>(xx);             // 2
    k_fc0<<<MROWS / FC_ROWS, 256>>>(W[0], al[0], ar[0]);         // 3
    k_agg<<<MROWS / 8, 256>>>();                                 // 4  <-- profiled
    k_wprep<<<dim3(HD, 3), HD>>>(W[1], W[2], W[3]);              // 5
    k_bnfin<<<1, HD>>>(gamma[0], beta[0]);                       // 6
    for (int l = 1; l < 4; l++) {
        k_gemm<<<ggrid, 512, GSM_BYTES>>>(l - 1, al[l], ar[l]);
        k_agg<<<MROWS / 8, 256>>>();
        k_bnfin<<<1, HD>>>(gamma[l], beta[l]);
    }
    k_proj<<<MROWS / 8, 256>>>(W_out, b_out, out, 0);

    for (int step = 1; step < TSTEPS; step++) {
        for (int l = 0; l < 4; l++) {
            if (l == 0)
                k_fc0<<<MROWS / FC_ROWS, 256>>>(W[0], al[0], ar[0]);
            else
                k_gemm<<<ggrid, 512, GSM_BYTES>>>(l - 1, al[l], ar[l]);
            k_agg<<<MROWS / 8, 256>>>();
            k_bnfin<<<1, HD>>>(gamma[l], beta[l]);
        }
        k_proj<<<MROWS / 8, 256>>>(W_out, b_out, out, step);
    }
}